// round 1
// baseline (speedup 1.0000x reference)
#include <cuda_runtime.h>
#include <math.h>

#define DIM 384
#define HEADS 12
#define HEAD_DIM 32
#define NTOK 131072          // 32*64*64 tokens
#define QKV_N 1152
#define MLP_HIDDEN 1536
#define ATT_SCALE 0.17677669529663687f   // 32^-0.5

// ---------------- scratch (static device globals; no allocations) -------------
__device__ float g_xt[NTOK * DIM];        // token-major input (shortcut)
__device__ float g_xw[NTOK * DIM];        // LN'd windowed tokens / reused buffers
__device__ float g_qkv[NTOK * QKV_N];     // qkv projections
__device__ float g_attout[NTOK * DIM];    // attention output (window order)
__device__ float g_proj[NTOK * DIM];      // proj output (window order)
__device__ float g_x1[NTOK * DIM];        // post-attention residual (token order)
__device__ float g_h[NTOK * MLP_HIDDEN];  // MLP hidden

// ---------------- transpose: (B,C,HW) -> (B,HW,C) ----------------------------
__global__ void transpose_in(const float* __restrict__ x, float* __restrict__ xt) {
    __shared__ float tile[32][33];
    int b = blockIdx.z;
    int c0 = blockIdx.y * 32;
    int p0 = blockIdx.x * 32;
    const float* xb = x + (size_t)b * DIM * 4096;
    float* xtb = xt + (size_t)b * 4096 * DIM;
    int tx = threadIdx.x, ty = threadIdx.y;
#pragma unroll
    for (int i = 0; i < 32; i += 8)
        tile[ty + i][tx] = xb[(size_t)(c0 + ty + i) * 4096 + p0 + tx];
    __syncthreads();
#pragma unroll
    for (int i = 0; i < 32; i += 8)
        xtb[(size_t)(p0 + ty + i) * DIM + c0 + tx] = tile[tx][ty + i];
}

// ---------------- transpose back: (B,HW,C) -> (B,C,HW) ------------------------
__global__ void transpose_out(const float* __restrict__ xt, float* __restrict__ y) {
    __shared__ float tile[32][33];
    int b = blockIdx.z;
    int c0 = blockIdx.y * 32;
    int p0 = blockIdx.x * 32;
    const float* xb = xt + (size_t)b * 4096 * DIM;
    float* yb = y + (size_t)b * DIM * 4096;
    int tx = threadIdx.x, ty = threadIdx.y;
#pragma unroll
    for (int i = 0; i < 32; i += 8)
        tile[ty + i][tx] = xb[(size_t)(p0 + ty + i) * DIM + c0 + tx];
    __syncthreads();
#pragma unroll
    for (int i = 0; i < 32; i += 8)
        yb[(size_t)(c0 + ty + i) * 4096 + p0 + tx] = tile[tx][ty + i];
}

// ---------------- LayerNorm (+optional shift+window gather) ------------------
// One warp per output row. WINDOWED: output row p is window-ordered, source is
// the shifted (roll -4,-4) token. Otherwise identity row mapping.
template <bool WINDOWED>
__global__ void ln_kernel(const float* __restrict__ src,
                          const float* __restrict__ gamma,
                          const float* __restrict__ beta,
                          float* __restrict__ dst) {
    int warp = (blockIdx.x * blockDim.x + threadIdx.x) >> 5;
    int lane = threadIdx.x & 31;
    if (warp >= NTOK) return;

    size_t srow;
    if (WINDOWED) {
        int pos = warp & 63;
        int win = (warp >> 6) & 63;
        int b = warp >> 12;
        int iy = pos >> 3, ix = pos & 7;
        int wy = win >> 3, wx = win & 7;
        int hs = (wy * 8 + iy + 4) & 63;   // roll(-4)
        int ws = (wx * 8 + ix + 4) & 63;
        srow = ((size_t)b * 4096 + hs * 64 + ws) * DIM;
    } else {
        srow = (size_t)warp * DIM;
    }
    const float* row = src + srow;

    float vals[12];
    float s = 0.f;
#pragma unroll
    for (int k = 0; k < 12; k++) { vals[k] = row[lane + k * 32]; s += vals[k]; }
#pragma unroll
    for (int o = 16; o; o >>= 1) s += __shfl_xor_sync(0xffffffffu, s, o);
    float mu = s * (1.f / 384.f);
    float vv = 0.f;
#pragma unroll
    for (int k = 0; k < 12; k++) { float d = vals[k] - mu; vv += d * d; }
#pragma unroll
    for (int o = 16; o; o >>= 1) vv += __shfl_xor_sync(0xffffffffu, vv, o);
    float rstd = rsqrtf(vv * (1.f / 384.f) + 1e-5f);

    float* orow = dst + (size_t)warp * DIM;
#pragma unroll
    for (int k = 0; k < 12; k++) {
        int c = lane + k * 32;
        orow[c] = (vals[k] - mu) * rstd * gamma[c] + beta[c];
    }
}

// ---------------- window reverse + unshift + residual ------------------------
__global__ void resid_reverse(const float* __restrict__ xt,
                              const float* __restrict__ proj,
                              float* __restrict__ x1) {
    int t = blockIdx.x;
    int b = t >> 12, hw = t & 4095;
    int h = hw >> 6, w = hw & 63;
    int hh = (h + 60) & 63;   // roll(+4): read from (h-4) mod 64
    int ww = (w + 60) & 63;
    int win = (hh >> 3) * 8 + (ww >> 3);
    int pos = (hh & 7) * 8 + (ww & 7);
    size_t srow = ((size_t)(b * 64 + win) * 64 + pos) * DIM;
    size_t drow = (size_t)t * DIM;
    for (int c = threadIdx.x; c < DIM; c += blockDim.x)
        x1[drow + c] = xt[drow + c] + proj[srow + c];
}

// ---------------- fused windowed attention ------------------------------------
// One block per (window, head). N=64 tokens, d=32. Everything in SMEM.
__device__ __forceinline__ int region64(int v) { return v < 56 ? 0 : (v < 60 ? 1 : 2); }

__global__ __launch_bounds__(256) void attn_kernel(const float* __restrict__ qkv,
                                                   const float* __restrict__ rel_bias,
                                                   float* __restrict__ out) {
    __shared__ float Qs[32][64];   // [d][n]
    __shared__ float Ks[32][64];   // [d][n]
    __shared__ float Vs[64][32];   // [n][d]
    __shared__ float S[64][65];

    int blk = blockIdx.x;
    int win = blk / HEADS;
    int head = blk - win * HEADS;
    int tid = threadIdx.x;

    const float* base = qkv + (size_t)win * 64 * QKV_N + head * HEAD_DIM;
    {
        int n = tid >> 2;
        int d0 = (tid & 3) << 3;
        const float* qrow = base + (size_t)n * QKV_N;
        float4 q0 = *(const float4*)(qrow + d0);
        float4 q1 = *(const float4*)(qrow + d0 + 4);
        Qs[d0 + 0][n] = q0.x; Qs[d0 + 1][n] = q0.y; Qs[d0 + 2][n] = q0.z; Qs[d0 + 3][n] = q0.w;
        Qs[d0 + 4][n] = q1.x; Qs[d0 + 5][n] = q1.y; Qs[d0 + 6][n] = q1.z; Qs[d0 + 7][n] = q1.w;
        float4 k0 = *(const float4*)(qrow + DIM + d0);
        float4 k1 = *(const float4*)(qrow + DIM + d0 + 4);
        Ks[d0 + 0][n] = k0.x; Ks[d0 + 1][n] = k0.y; Ks[d0 + 2][n] = k0.z; Ks[d0 + 3][n] = k0.w;
        Ks[d0 + 4][n] = k1.x; Ks[d0 + 5][n] = k1.y; Ks[d0 + 6][n] = k1.z; Ks[d0 + 7][n] = k1.w;
        float4 v0 = *(const float4*)(qrow + 2 * DIM + d0);
        float4 v1 = *(const float4*)(qrow + 2 * DIM + d0 + 4);
        *(float4*)&Vs[n][d0] = v0;
        *(float4*)&Vs[n][d0 + 4] = v1;
    }
    __syncthreads();

    // S[r][c] = scale * sum_d Q[r][d]*K[c][d] + rel_bias + shift mask
    int mr = (tid >> 4) << 2;
    int nc = (tid & 15) << 2;
    float acc[4][4] = {};
#pragma unroll
    for (int d = 0; d < 32; d++) {
        float a[4], bfr[4];
        *(float4*)a = *(const float4*)&Qs[d][mr];
        *(float4*)bfr = *(const float4*)&Ks[d][nc];
#pragma unroll
        for (int i = 0; i < 4; i++)
#pragma unroll
            for (int j = 0; j < 4; j++) acc[i][j] += a[i] * bfr[j];
    }
    int win_img = win & 63;
    int wy = win_img >> 3, wx = win_img & 7;
#pragma unroll
    for (int i = 0; i < 4; i++) {
        int r = mr + i;
        int ry = r >> 3, rx = r & 7;
        int reg_r = region64(wy * 8 + ry) * 3 + region64(wx * 8 + rx);
#pragma unroll
        for (int j = 0; j < 4; j++) {
            int c = nc + j;
            int cy = c >> 3, cx = c & 7;
            int idx = (ry - cy + 7) * 15 + (rx - cx + 7);
            float bb = rel_bias[idx * HEADS + head];
            int reg_c = region64(wy * 8 + cy) * 3 + region64(wx * 8 + cx);
            float m = (reg_r != reg_c) ? -10.0f : 0.0f;
            S[r][c] = acc[i][j] * ATT_SCALE + bb + m;
        }
    }
    __syncthreads();

    // softmax rows: warp per row, 8 rows per warp
    int wid = tid >> 5, lane = tid & 31;
    for (int r = wid; r < 64; r += 8) {
        float v0 = S[r][lane], v1 = S[r][lane + 32];
        float mx = fmaxf(v0, v1);
#pragma unroll
        for (int o = 16; o; o >>= 1) mx = fmaxf(mx, __shfl_xor_sync(0xffffffffu, mx, o));
        float e0 = expf(v0 - mx), e1 = expf(v1 - mx);
        float sm = e0 + e1;
#pragma unroll
        for (int o = 16; o; o >>= 1) sm += __shfl_xor_sync(0xffffffffu, sm, o);
        float inv = 1.f / sm;
        S[r][lane] = e0 * inv;
        S[r][lane + 32] = e1 * inv;
    }
    __syncthreads();

    // O = P @ V : thread -> 2 rows x 4 cols
    int r2 = (tid >> 3) << 1;
    int c2 = (tid & 7) << 2;
    float o0[4] = {}, o1[4] = {};
#pragma unroll
    for (int m = 0; m < 64; m++) {
        float s0 = S[r2][m], s1 = S[r2 + 1][m];
        float4 vv = *(const float4*)&Vs[m][c2];
        o0[0] += s0 * vv.x; o0[1] += s0 * vv.y; o0[2] += s0 * vv.z; o0[3] += s0 * vv.w;
        o1[0] += s1 * vv.x; o1[1] += s1 * vv.y; o1[2] += s1 * vv.z; o1[3] += s1 * vv.w;
    }
    float* optr = out + ((size_t)(win * 64 + r2)) * DIM + head * HEAD_DIM + c2;
    *(float4*)optr = make_float4(o0[0], o0[1], o0[2], o0[3]);
    *(float4*)(optr + DIM) = make_float4(o1[0], o1[1], o1[2], o1[3]);
}

// ---------------- fp32 SGEMM 128x128x16, 256 threads, 8x8 microtile ----------
// C[M,N] = A[M,K] (row-major) * B[K,N] (row-major) + bias[N], with epilogue:
//   MODE 0: plain    MODE 1: exact GELU    MODE 2: + res[m*384+n]
template <int MODE>
__global__ __launch_bounds__(256) void sgemm(const float* __restrict__ A,
                                             const float* __restrict__ B,
                                             const float* __restrict__ bias,
                                             const float* __restrict__ res,
                                             float* __restrict__ C,
                                             int M, int N, int K) {
    __shared__ float As[16][128];
    __shared__ float Bs[16][128];
    int tid = threadIdx.x;
    int bm = blockIdx.y * 128;
    int bn = blockIdx.x * 128;

    int a_row = tid >> 2;
    int a_col = (tid & 3) << 2;
    int b_row = tid >> 5;
    int b_col = (tid & 31) << 2;

    int tx = (tid & 15) << 3;
    int ty = (tid >> 4) << 3;

    float acc[8][8] = {};

    for (int kt = 0; kt < K; kt += 16) {
        float4 av0 = *(const float4*)(A + (size_t)(bm + a_row) * K + kt + a_col);
        float4 av1 = *(const float4*)(A + (size_t)(bm + a_row + 64) * K + kt + a_col);
        As[a_col + 0][a_row] = av0.x; As[a_col + 1][a_row] = av0.y;
        As[a_col + 2][a_row] = av0.z; As[a_col + 3][a_row] = av0.w;
        As[a_col + 0][a_row + 64] = av1.x; As[a_col + 1][a_row + 64] = av1.y;
        As[a_col + 2][a_row + 64] = av1.z; As[a_col + 3][a_row + 64] = av1.w;
        float4 bv0 = *(const float4*)(B + (size_t)(kt + b_row) * N + bn + b_col);
        float4 bv1 = *(const float4*)(B + (size_t)(kt + b_row + 8) * N + bn + b_col);
        *(float4*)&Bs[b_row][b_col] = bv0;
        *(float4*)&Bs[b_row + 8][b_col] = bv1;
        __syncthreads();
#pragma unroll
        for (int k = 0; k < 16; k++) {
            float ar[8], br[8];
            *(float4*)ar       = *(const float4*)&As[k][ty];
            *(float4*)(ar + 4) = *(const float4*)&As[k][ty + 4];
            *(float4*)br       = *(const float4*)&Bs[k][tx];
            *(float4*)(br + 4) = *(const float4*)&Bs[k][tx + 4];
#pragma unroll
            for (int i = 0; i < 8; i++)
#pragma unroll
                for (int j = 0; j < 8; j++) acc[i][j] += ar[i] * br[j];
        }
        __syncthreads();
    }

#pragma unroll
    for (int i = 0; i < 8; i++) {
        int m = bm + ty + i;
        size_t crow = (size_t)m * N;
#pragma unroll
        for (int j = 0; j < 8; j++) {
            int n = bn + tx + j;
            float v = acc[i][j] + bias[n];
            if (MODE == 1) {
                v = 0.5f * v * (1.0f + erff(v * 0.7071067811865476f));
            } else if (MODE == 2) {
                v += res[(size_t)m * DIM + n];
            }
            C[crow + n] = v;
        }
    }
}

// ---------------- launcher -----------------------------------------------------
extern "C" void kernel_launch(void* const* d_in, const int* in_sizes, int n_in,
                              void* d_out, int out_size) {
    const float* x       = (const float*)d_in[0];
    const float* qkv_w   = (const float*)d_in[1];
    const float* qkv_b   = (const float*)d_in[2];
    const float* proj_w  = (const float*)d_in[3];
    const float* proj_b  = (const float*)d_in[4];
    const float* rel_bias= (const float*)d_in[5];
    const float* norm1_g = (const float*)d_in[6];
    const float* norm1_b = (const float*)d_in[7];
    const float* norm2_g = (const float*)d_in[8];
    const float* norm2_b = (const float*)d_in[9];
    const float* fc1_w   = (const float*)d_in[10];
    const float* fc1_b   = (const float*)d_in[11];
    const float* fc2_w   = (const float*)d_in[12];
    const float* fc2_b   = (const float*)d_in[13];

    float *xt, *xw, *qkv, *attout, *proj, *x1, *h;
    cudaGetSymbolAddress((void**)&xt, g_xt);
    cudaGetSymbolAddress((void**)&xw, g_xw);
    cudaGetSymbolAddress((void**)&qkv, g_qkv);
    cudaGetSymbolAddress((void**)&attout, g_attout);
    cudaGetSymbolAddress((void**)&proj, g_proj);
    cudaGetSymbolAddress((void**)&x1, g_x1);
    cudaGetSymbolAddress((void**)&h, g_h);

    // 1. BCHW -> token-major (shortcut)
    transpose_in<<<dim3(128, 12, 32), dim3(32, 8)>>>(x, xt);
    // 2. LN1 + shift + window partition
    ln_kernel<true><<<NTOK / 8, 256>>>(xt, norm1_g, norm1_b, xw);
    // 3. QKV projection
    sgemm<0><<<dim3(QKV_N / 128, NTOK / 128), 256>>>(xw, qkv_w, qkv_b, nullptr, qkv,
                                                     NTOK, QKV_N, DIM);
    // 4. windowed attention (fused bias/mask/softmax)
    attn_kernel<<<2048 * HEADS, 256>>>(qkv, rel_bias, attout);
    // 5. output projection
    sgemm<0><<<dim3(DIM / 128, NTOK / 128), 256>>>(attout, proj_w, proj_b, nullptr, proj,
                                                   NTOK, DIM, DIM);
    // 6. window reverse + unshift + residual
    resid_reverse<<<NTOK, 128>>>(xt, proj, x1);
    // 7. LN2
    ln_kernel<false><<<NTOK / 8, 256>>>(x1, norm2_g, norm2_b, xw);
    // 8. FC1 + GELU
    sgemm<1><<<dim3(MLP_HIDDEN / 128, NTOK / 128), 256>>>(xw, fc1_w, fc1_b, nullptr, h,
                                                          NTOK, MLP_HIDDEN, DIM);
    // 9. FC2 + residual (token-major)
    sgemm<2><<<dim3(DIM / 128, NTOK / 128), 256>>>(h, fc2_w, fc2_b, x1, xw,
                                                   NTOK, DIM, MLP_HIDDEN);
    // 10. token-major -> BCHW
    transpose_out<<<dim3(128, 12, 32), dim3(32, 8)>>>(xw, (float*)d_out);
}

// round 3
// speedup vs baseline: 2.9121x; 2.9121x over previous
#include <cuda_runtime.h>
#include <cstdint>
#include <math.h>

#define DIM 384
#define HEADS 12
#define HEAD_DIM 32
#define NTOK 131072          // 32*64*64 tokens
#define QKV_N 1152
#define MLP_HIDDEN 1536
#define ATT_SCALE 0.17677669529663687f   // 32^-0.5

// ---------------- scratch (static device globals; no allocations) -------------
__device__ float g_xt[NTOK * DIM];        // token-major input (shortcut)
__device__ float g_xw[NTOK * DIM];        // LN'd windowed tokens / reused buffers
__device__ float g_qkv[NTOK * QKV_N];     // qkv projections
__device__ float g_attout[NTOK * DIM];    // attention output (window order)
__device__ float g_proj[NTOK * DIM];      // proj output (window order)
__device__ float g_x1[NTOK * DIM];        // post-attention residual (token order)
__device__ float g_h[NTOK * MLP_HIDDEN];  // MLP hidden

// ---------------- transpose: (B,C,HW) -> (B,HW,C) ----------------------------
__global__ void transpose_in(const float* __restrict__ x, float* __restrict__ xt) {
    __shared__ float tile[32][33];
    int b = blockIdx.z;
    int c0 = blockIdx.y * 32;
    int p0 = blockIdx.x * 32;
    const float* xb = x + (size_t)b * DIM * 4096;
    float* xtb = xt + (size_t)b * 4096 * DIM;
    int tx = threadIdx.x, ty = threadIdx.y;
#pragma unroll
    for (int i = 0; i < 32; i += 8)
        tile[ty + i][tx] = xb[(size_t)(c0 + ty + i) * 4096 + p0 + tx];
    __syncthreads();
#pragma unroll
    for (int i = 0; i < 32; i += 8)
        xtb[(size_t)(p0 + ty + i) * DIM + c0 + tx] = tile[tx][ty + i];
}

// ---------------- transpose back: (B,HW,C) -> (B,C,HW) ------------------------
__global__ void transpose_out(const float* __restrict__ xt, float* __restrict__ y) {
    __shared__ float tile[32][33];
    int b = blockIdx.z;
    int c0 = blockIdx.y * 32;
    int p0 = blockIdx.x * 32;
    const float* xb = xt + (size_t)b * 4096 * DIM;
    float* yb = y + (size_t)b * DIM * 4096;
    int tx = threadIdx.x, ty = threadIdx.y;
#pragma unroll
    for (int i = 0; i < 32; i += 8)
        tile[ty + i][tx] = xb[(size_t)(p0 + ty + i) * DIM + c0 + tx];
    __syncthreads();
#pragma unroll
    for (int i = 0; i < 32; i += 8)
        yb[(size_t)(c0 + ty + i) * 4096 + p0 + tx] = tile[tx][ty + i];
}

// ---------------- LayerNorm (+optional shift+window gather) ------------------
template <bool WINDOWED>
__global__ void ln_kernel(const float* __restrict__ src,
                          const float* __restrict__ gamma,
                          const float* __restrict__ beta,
                          float* __restrict__ dst) {
    int warp = (blockIdx.x * blockDim.x + threadIdx.x) >> 5;
    int lane = threadIdx.x & 31;
    if (warp >= NTOK) return;

    size_t srow;
    if (WINDOWED) {
        int pos = warp & 63;
        int win = (warp >> 6) & 63;
        int b = warp >> 12;
        int iy = pos >> 3, ix = pos & 7;
        int wy = win >> 3, wx = win & 7;
        int hs = (wy * 8 + iy + 4) & 63;   // roll(-4)
        int ws = (wx * 8 + ix + 4) & 63;
        srow = ((size_t)b * 4096 + hs * 64 + ws) * DIM;
    } else {
        srow = (size_t)warp * DIM;
    }
    const float* row = src + srow;

    float vals[12];
    float s = 0.f;
#pragma unroll
    for (int k = 0; k < 12; k++) { vals[k] = row[lane + k * 32]; s += vals[k]; }
#pragma unroll
    for (int o = 16; o; o >>= 1) s += __shfl_xor_sync(0xffffffffu, s, o);
    float mu = s * (1.f / 384.f);
    float vv = 0.f;
#pragma unroll
    for (int k = 0; k < 12; k++) { float d = vals[k] - mu; vv += d * d; }
#pragma unroll
    for (int o = 16; o; o >>= 1) vv += __shfl_xor_sync(0xffffffffu, vv, o);
    float rstd = rsqrtf(vv * (1.f / 384.f) + 1e-5f);

    float* orow = dst + (size_t)warp * DIM;
#pragma unroll
    for (int k = 0; k < 12; k++) {
        int c = lane + k * 32;
        orow[c] = (vals[k] - mu) * rstd * gamma[c] + beta[c];
    }
}

// ---------------- window reverse + unshift + residual ------------------------
__global__ void resid_reverse(const float* __restrict__ xt,
                              const float* __restrict__ proj,
                              float* __restrict__ x1) {
    int t = blockIdx.x;
    int b = t >> 12, hw = t & 4095;
    int h = hw >> 6, w = hw & 63;
    int hh = (h + 60) & 63;   // roll(+4)
    int ww = (w + 60) & 63;
    int win = (hh >> 3) * 8 + (ww >> 3);
    int pos = (hh & 7) * 8 + (ww & 7);
    size_t srow = ((size_t)(b * 64 + win) * 64 + pos) * DIM;
    size_t drow = (size_t)t * DIM;
    for (int c = threadIdx.x; c < DIM; c += blockDim.x)
        x1[drow + c] = xt[drow + c] + proj[srow + c];
}

// ---------------- fused windowed attention ------------------------------------
__device__ __forceinline__ int region64(int v) { return v < 56 ? 0 : (v < 60 ? 1 : 2); }

__global__ __launch_bounds__(256) void attn_kernel(const float* __restrict__ qkv,
                                                   const float* __restrict__ rel_bias,
                                                   float* __restrict__ out) {
    __shared__ float Qs[32][64];
    __shared__ float Ks[32][64];
    __shared__ float Vs[64][32];
    __shared__ float S[64][65];

    int blk = blockIdx.x;
    int win = blk / HEADS;
    int head = blk - win * HEADS;
    int tid = threadIdx.x;

    const float* base = qkv + (size_t)win * 64 * QKV_N + head * HEAD_DIM;
    {
        int n = tid >> 2;
        int d0 = (tid & 3) << 3;
        const float* qrow = base + (size_t)n * QKV_N;
        float4 q0 = *(const float4*)(qrow + d0);
        float4 q1 = *(const float4*)(qrow + d0 + 4);
        Qs[d0 + 0][n] = q0.x; Qs[d0 + 1][n] = q0.y; Qs[d0 + 2][n] = q0.z; Qs[d0 + 3][n] = q0.w;
        Qs[d0 + 4][n] = q1.x; Qs[d0 + 5][n] = q1.y; Qs[d0 + 6][n] = q1.z; Qs[d0 + 7][n] = q1.w;
        float4 k0 = *(const float4*)(qrow + DIM + d0);
        float4 k1 = *(const float4*)(qrow + DIM + d0 + 4);
        Ks[d0 + 0][n] = k0.x; Ks[d0 + 1][n] = k0.y; Ks[d0 + 2][n] = k0.z; Ks[d0 + 3][n] = k0.w;
        Ks[d0 + 4][n] = k1.x; Ks[d0 + 5][n] = k1.y; Ks[d0 + 6][n] = k1.z; Ks[d0 + 7][n] = k1.w;
        float4 v0 = *(const float4*)(qrow + 2 * DIM + d0);
        float4 v1 = *(const float4*)(qrow + 2 * DIM + d0 + 4);
        *(float4*)&Vs[n][d0] = v0;
        *(float4*)&Vs[n][d0 + 4] = v1;
    }
    __syncthreads();

    int mr = (tid >> 4) << 2;
    int nc = (tid & 15) << 2;
    float acc[4][4] = {};
#pragma unroll
    for (int d = 0; d < 32; d++) {
        float a[4], bfr[4];
        *(float4*)a = *(const float4*)&Qs[d][mr];
        *(float4*)bfr = *(const float4*)&Ks[d][nc];
#pragma unroll
        for (int i = 0; i < 4; i++)
#pragma unroll
            for (int j = 0; j < 4; j++) acc[i][j] += a[i] * bfr[j];
    }
    int win_img = win & 63;
    int wy = win_img >> 3, wx = win_img & 7;
#pragma unroll
    for (int i = 0; i < 4; i++) {
        int r = mr + i;
        int ry = r >> 3, rx = r & 7;
        int reg_r = region64(wy * 8 + ry) * 3 + region64(wx * 8 + rx);
#pragma unroll
        for (int j = 0; j < 4; j++) {
            int c = nc + j;
            int cy = c >> 3, cx = c & 7;
            int idx = (ry - cy + 7) * 15 + (rx - cx + 7);
            float bb = rel_bias[idx * HEADS + head];
            int reg_c = region64(wy * 8 + cy) * 3 + region64(wx * 8 + cx);
            float m = (reg_r != reg_c) ? -10.0f : 0.0f;
            S[r][c] = acc[i][j] * ATT_SCALE + bb + m;
        }
    }
    __syncthreads();

    int wid = tid >> 5, lane = tid & 31;
    for (int r = wid; r < 64; r += 8) {
        float v0 = S[r][lane], v1 = S[r][lane + 32];
        float mx = fmaxf(v0, v1);
#pragma unroll
        for (int o = 16; o; o >>= 1) mx = fmaxf(mx, __shfl_xor_sync(0xffffffffu, mx, o));
        float e0 = expf(v0 - mx), e1 = expf(v1 - mx);
        float sm = e0 + e1;
#pragma unroll
        for (int o = 16; o; o >>= 1) sm += __shfl_xor_sync(0xffffffffu, sm, o);
        float inv = 1.f / sm;
        S[r][lane] = e0 * inv;
        S[r][lane + 32] = e1 * inv;
    }
    __syncthreads();

    int r2 = (tid >> 3) << 1;
    int c2 = (tid & 7) << 2;
    float o0[4] = {}, o1[4] = {};
#pragma unroll
    for (int m = 0; m < 64; m++) {
        float s0 = S[r2][m], s1 = S[r2 + 1][m];
        float4 vv = *(const float4*)&Vs[m][c2];
        o0[0] += s0 * vv.x; o0[1] += s0 * vv.y; o0[2] += s0 * vv.z; o0[3] += s0 * vv.w;
        o1[0] += s1 * vv.x; o1[1] += s1 * vv.y; o1[2] += s1 * vv.z; o1[3] += s1 * vv.w;
    }
    float* optr = out + ((size_t)(win * 64 + r2)) * DIM + head * HEAD_DIM + c2;
    *(float4*)optr = make_float4(o0[0], o0[1], o0[2], o0[3]);
    *(float4*)(optr + DIM) = make_float4(o1[0], o1[1], o1[2], o1[3]);
}

// ================= tf32 tensor-core GEMM =====================================
// C[M,N] = A[M,K] * B[K,N] + bias, epilogue MODE: 0 plain, 1 GELU, 2 +res.
// Block 128x128, BK=16, 8 warps (4m x 2n), warp tile 32x64 (2x8 m16n8k8).
// Double-buffered smem via cp.async.cg; cvt.rna to tf32 after LDS.
#define BK 16
#define AS_STRIDE 20   // bank: 4*grp + lig -> conflict-free
#define BS_STRIDE 136  // bank: 8*lig + grp -> conflict-free
#define AS_ELEMS (128 * AS_STRIDE)
#define BS_ELEMS (BK * BS_STRIDE)

__device__ __forceinline__ unsigned f2tf32(float f) {
    unsigned u;
    asm("cvt.rna.tf32.f32 %0, %1;" : "=r"(u) : "f"(f));
    return u;
}

template <int MODE>
__global__ __launch_bounds__(256, 2) void tgemm(const float* __restrict__ A,
                                                const float* __restrict__ B,
                                                const float* __restrict__ bias,
                                                const float* __restrict__ res,
                                                float* __restrict__ C,
                                                int M, int N, int K) {
    __shared__ float As[2][AS_ELEMS];
    __shared__ float Bs[2][BS_ELEMS];

    const int tid = threadIdx.x;
    const int lane = tid & 31;
    const int wid = tid >> 5;
    const int grp = lane >> 2;      // 0..7
    const int lig = lane & 3;       // 0..3
    const int wm = wid & 3;         // 0..3
    const int wn = wid >> 2;        // 0..1
    const int bm = blockIdx.y * 128;
    const int bn = blockIdx.x * 128;

    // loader geometry
    const int a_r = tid >> 2;             // 0..63, +64
    const int a_c = (tid & 3) << 2;       // 0,4,8,12
    const int b_r = tid >> 5;             // 0..7, +8
    const int b_c = (tid & 31) << 2;      // 0..124

    float acc[2][8][4];
#pragma unroll
    for (int mt = 0; mt < 2; mt++)
#pragma unroll
        for (int nt = 0; nt < 8; nt++)
#pragma unroll
            for (int i = 0; i < 4; i++) acc[mt][nt][i] = 0.f;

    const int T = K / BK;

    // --- issue tile t into buffer buf ---
    auto issue = [&](int kt, int buf) {
#pragma unroll
        for (int i = 0; i < 2; i++) {
            int r = a_r + 64 * i;
            const float* g = A + (size_t)(bm + r) * K + kt + a_c;
            unsigned s = (unsigned)__cvta_generic_to_shared(&As[buf][r * AS_STRIDE + a_c]);
            asm volatile("cp.async.cg.shared.global [%0], [%1], 16;\n" :: "r"(s), "l"(g));
        }
#pragma unroll
        for (int i = 0; i < 2; i++) {
            int r = b_r + 8 * i;
            const float* g = B + (size_t)(kt + r) * N + bn + b_c;
            unsigned s = (unsigned)__cvta_generic_to_shared(&Bs[buf][r * BS_STRIDE + b_c]);
            asm volatile("cp.async.cg.shared.global [%0], [%1], 16;\n" :: "r"(s), "l"(g));
        }
        asm volatile("cp.async.commit_group;\n");
    };

    issue(0, 0);

    for (int t = 0; t < T; t++) {
        if (t + 1 < T) {
            issue((t + 1) * BK, (t + 1) & 1);
            asm volatile("cp.async.wait_group 1;\n");
        } else {
            asm volatile("cp.async.wait_group 0;\n");
        }
        __syncthreads();

        const float* Ab = As[t & 1];
        const float* Bb = Bs[t & 1];

#pragma unroll
        for (int kk = 0; kk < 2; kk++) {
            int k0 = kk * 8;
            unsigned af[2][4], bf[8][2];
#pragma unroll
            for (int mt = 0; mt < 2; mt++) {
                int rm = wm * 32 + mt * 16 + grp;
                af[mt][0] = f2tf32(Ab[rm * AS_STRIDE + k0 + lig]);
                af[mt][1] = f2tf32(Ab[(rm + 8) * AS_STRIDE + k0 + lig]);
                af[mt][2] = f2tf32(Ab[rm * AS_STRIDE + k0 + lig + 4]);
                af[mt][3] = f2tf32(Ab[(rm + 8) * AS_STRIDE + k0 + lig + 4]);
            }
#pragma unroll
            for (int nt = 0; nt < 8; nt++) {
                int cn = wn * 64 + nt * 8 + grp;
                bf[nt][0] = f2tf32(Bb[(k0 + lig) * BS_STRIDE + cn]);
                bf[nt][1] = f2tf32(Bb[(k0 + lig + 4) * BS_STRIDE + cn]);
            }
#pragma unroll
            for (int mt = 0; mt < 2; mt++)
#pragma unroll
                for (int nt = 0; nt < 8; nt++) {
                    asm volatile(
                        "mma.sync.aligned.m16n8k8.row.col.f32.tf32.tf32.f32 "
                        "{%0,%1,%2,%3}, {%4,%5,%6,%7}, {%8,%9}, {%0,%1,%2,%3};\n"
                        : "+f"(acc[mt][nt][0]), "+f"(acc[mt][nt][1]),
                          "+f"(acc[mt][nt][2]), "+f"(acc[mt][nt][3])
                        : "r"(af[mt][0]), "r"(af[mt][1]), "r"(af[mt][2]), "r"(af[mt][3]),
                          "r"(bf[nt][0]), "r"(bf[nt][1]));
                }
        }
        __syncthreads();
    }

    // epilogue: c0:(grp,2l) c1:(grp,2l+1) c2:(grp+8,2l) c3:(grp+8,2l+1)
#pragma unroll
    for (int mt = 0; mt < 2; mt++) {
#pragma unroll
        for (int half = 0; half < 2; half++) {
            int m = bm + wm * 32 + mt * 16 + grp + half * 8;
            size_t crow = (size_t)m * N;
#pragma unroll
            for (int nt = 0; nt < 8; nt++) {
                int n = bn + wn * 64 + nt * 8 + lig * 2;
                float v0 = acc[mt][nt][half * 2 + 0] + bias[n];
                float v1 = acc[mt][nt][half * 2 + 1] + bias[n + 1];
                if (MODE == 1) {
                    v0 = 0.5f * v0 * (1.0f + erff(v0 * 0.7071067811865476f));
                    v1 = 0.5f * v1 * (1.0f + erff(v1 * 0.7071067811865476f));
                } else if (MODE == 2) {
                    v0 += res[(size_t)m * DIM + n];
                    v1 += res[(size_t)m * DIM + n + 1];
                }
                *(float2*)&C[crow + n] = make_float2(v0, v1);
            }
        }
    }
}

// ---------------- launcher -----------------------------------------------------
extern "C" void kernel_launch(void* const* d_in, const int* in_sizes, int n_in,
                              void* d_out, int out_size) {
    const float* x       = (const float*)d_in[0];
    const float* qkv_w   = (const float*)d_in[1];
    const float* qkv_b   = (const float*)d_in[2];
    const float* proj_w  = (const float*)d_in[3];
    const float* proj_b  = (const float*)d_in[4];
    const float* rel_bias= (const float*)d_in[5];
    const float* norm1_g = (const float*)d_in[6];
    const float* norm1_b = (const float*)d_in[7];
    const float* norm2_g = (const float*)d_in[8];
    const float* norm2_b = (const float*)d_in[9];
    const float* fc1_w   = (const float*)d_in[10];
    const float* fc1_b   = (const float*)d_in[11];
    const float* fc2_w   = (const float*)d_in[12];
    const float* fc2_b   = (const float*)d_in[13];

    float *xt, *xw, *qkv, *attout, *proj, *x1, *h;
    cudaGetSymbolAddress((void**)&xt, g_xt);
    cudaGetSymbolAddress((void**)&xw, g_xw);
    cudaGetSymbolAddress((void**)&qkv, g_qkv);
    cudaGetSymbolAddress((void**)&attout, g_attout);
    cudaGetSymbolAddress((void**)&proj, g_proj);
    cudaGetSymbolAddress((void**)&x1, g_x1);
    cudaGetSymbolAddress((void**)&h, g_h);

    // 1. BCHW -> token-major (shortcut)
    transpose_in<<<dim3(128, 12, 32), dim3(32, 8)>>>(x, xt);
    // 2. LN1 + shift + window partition
    ln_kernel<true><<<NTOK / 8, 256>>>(xt, norm1_g, norm1_b, xw);
    // 3. QKV projection (tf32 tensor cores)
    tgemm<0><<<dim3(QKV_N / 128, NTOK / 128), 256>>>(xw, qkv_w, qkv_b, nullptr, qkv,
                                                     NTOK, QKV_N, DIM);
    // 4. windowed attention (fused bias/mask/softmax)
    attn_kernel<<<2048 * HEADS, 256>>>(qkv, rel_bias, attout);
    // 5. output projection
    tgemm<0><<<dim3(DIM / 128, NTOK / 128), 256>>>(attout, proj_w, proj_b, nullptr, proj,
                                                   NTOK, DIM, DIM);
    // 6. window reverse + unshift + residual
    resid_reverse<<<NTOK, 128>>>(xt, proj, x1);
    // 7. LN2
    ln_kernel<false><<<NTOK / 8, 256>>>(x1, norm2_g, norm2_b, xw);
    // 8. FC1 + GELU
    tgemm<1><<<dim3(MLP_HIDDEN / 128, NTOK / 128), 256>>>(xw, fc1_w, fc1_b, nullptr, h,
                                                          NTOK, MLP_HIDDEN, DIM);
    // 9. FC2 + residual (token-major)
    tgemm<2><<<dim3(DIM / 128, NTOK / 128), 256>>>(h, fc2_w, fc2_b, x1, xw,
                                                   NTOK, DIM, MLP_HIDDEN);
    // 10. token-major -> BCHW
    transpose_out<<<dim3(128, 12, 32), dim3(32, 8)>>>(xw, (float*)d_out);
}

// round 5
// speedup vs baseline: 4.0775x; 1.4002x over previous
#include <cuda_runtime.h>
#include <cuda_fp16.h>
#include <cstdint>
#include <math.h>

#define DIM 384
#define HEADS 12
#define HEAD_DIM 32
#define NTOK 131072          // 32*64*64 tokens
#define QKV_N 1152
#define MLP_HIDDEN 1536
#define ATT_SCALE 0.17677669529663687f   // 32^-0.5

// ---------------- scratch (static device globals; no allocations) -------------
__device__ float  g_xt[NTOK * DIM];           // token-major input (shortcut)
__device__ __half g_xw[NTOK * DIM];           // LN output (GEMM A input)
__device__ float  g_qkv[NTOK * QKV_N];        // qkv projections
__device__ __half g_attout[NTOK * DIM];       // attention output (GEMM A input)
__device__ float  g_proj[NTOK * DIM];         // proj output / reused as FC2 out
__device__ float  g_x1[NTOK * DIM];           // post-attention residual
__device__ __half g_h[NTOK * MLP_HIDDEN];     // MLP hidden (GEMM A input)
// transposed (N,K) weights in fp16
__device__ __half g_wt_qkv[QKV_N * DIM];
__device__ __half g_wt_proj[DIM * DIM];
__device__ __half g_wt_fc1[MLP_HIDDEN * DIM];
__device__ __half g_wt_fc2[DIM * MLP_HIDDEN];

// ---------------- transpose: (B,C,HW) -> (B,HW,C) ----------------------------
__global__ void transpose_in(const float* __restrict__ x, float* __restrict__ xt) {
    __shared__ float tile[32][33];
    int b = blockIdx.z;
    int c0 = blockIdx.y * 32;
    int p0 = blockIdx.x * 32;
    const float* xb = x + (size_t)b * DIM * 4096;
    float* xtb = xt + (size_t)b * 4096 * DIM;
    int tx = threadIdx.x, ty = threadIdx.y;
#pragma unroll
    for (int i = 0; i < 32; i += 8)
        tile[ty + i][tx] = xb[(size_t)(c0 + ty + i) * 4096 + p0 + tx];
    __syncthreads();
#pragma unroll
    for (int i = 0; i < 32; i += 8)
        xtb[(size_t)(p0 + ty + i) * DIM + c0 + tx] = tile[tx][ty + i];
}

__global__ void transpose_out(const float* __restrict__ xt, float* __restrict__ y) {
    __shared__ float tile[32][33];
    int b = blockIdx.z;
    int c0 = blockIdx.y * 32;
    int p0 = blockIdx.x * 32;
    const float* xb = xt + (size_t)b * 4096 * DIM;
    float* yb = y + (size_t)b * DIM * 4096;
    int tx = threadIdx.x, ty = threadIdx.y;
#pragma unroll
    for (int i = 0; i < 32; i += 8)
        tile[ty + i][tx] = xb[(size_t)(p0 + ty + i) * DIM + c0 + tx];
    __syncthreads();
#pragma unroll
    for (int i = 0; i < 32; i += 8)
        yb[(size_t)(c0 + ty + i) * 4096 + p0 + tx] = tile[tx][ty + i];
}

// ---------------- weight transpose (K,N)->(N,K) fp16 -------------------------
__global__ void transpose_w(const float* __restrict__ W, __half* __restrict__ Wt,
                            int K, int N) {
    __shared__ float tile[32][33];
    int k0 = blockIdx.y * 32;
    int n0 = blockIdx.x * 32;
    int tx = threadIdx.x, ty = threadIdx.y;
#pragma unroll
    for (int i = 0; i < 32; i += 8)
        tile[ty + i][tx] = W[(size_t)(k0 + ty + i) * N + n0 + tx];
    __syncthreads();
#pragma unroll
    for (int i = 0; i < 32; i += 8)
        Wt[(size_t)(n0 + ty + i) * K + k0 + tx] = __float2half_rn(tile[tx][ty + i]);
}

// ---------------- LayerNorm (+optional shift+window gather) ------------------
template <bool WINDOWED>
__global__ void ln_kernel(const float* __restrict__ src,
                          const float* __restrict__ gamma,
                          const float* __restrict__ beta,
                          __half* __restrict__ dst) {
    int warp = (blockIdx.x * blockDim.x + threadIdx.x) >> 5;
    int lane = threadIdx.x & 31;
    if (warp >= NTOK) return;

    size_t srow;
    if (WINDOWED) {
        int pos = warp & 63;
        int win = (warp >> 6) & 63;
        int b = warp >> 12;
        int iy = pos >> 3, ix = pos & 7;
        int wy = win >> 3, wx = win & 7;
        int hs = (wy * 8 + iy + 4) & 63;   // roll(-4)
        int ws = (wx * 8 + ix + 4) & 63;
        srow = ((size_t)b * 4096 + hs * 64 + ws) * DIM;
    } else {
        srow = (size_t)warp * DIM;
    }
    const float* row = src + srow;

    float vals[12];
    float s = 0.f;
#pragma unroll
    for (int k = 0; k < 12; k++) { vals[k] = row[lane + k * 32]; s += vals[k]; }
#pragma unroll
    for (int o = 16; o; o >>= 1) s += __shfl_xor_sync(0xffffffffu, s, o);
    float mu = s * (1.f / 384.f);
    float vv = 0.f;
#pragma unroll
    for (int k = 0; k < 12; k++) { float d = vals[k] - mu; vv += d * d; }
#pragma unroll
    for (int o = 16; o; o >>= 1) vv += __shfl_xor_sync(0xffffffffu, vv, o);
    float rstd = rsqrtf(vv * (1.f / 384.f) + 1e-5f);

    __half* orow = dst + (size_t)warp * DIM;
#pragma unroll
    for (int k = 0; k < 12; k++) {
        int c = lane + k * 32;
        orow[c] = __float2half_rn((vals[k] - mu) * rstd * gamma[c] + beta[c]);
    }
}

// ---------------- window reverse + unshift + residual ------------------------
__global__ void resid_reverse(const float* __restrict__ xt,
                              const float* __restrict__ proj,
                              float* __restrict__ x1) {
    int t = blockIdx.x;
    int b = t >> 12, hw = t & 4095;
    int h = hw >> 6, w = hw & 63;
    int hh = (h + 60) & 63;
    int ww = (w + 60) & 63;
    int win = (hh >> 3) * 8 + (ww >> 3);
    int pos = (hh & 7) * 8 + (ww & 7);
    size_t srow = ((size_t)(b * 64 + win) * 64 + pos) * DIM;
    size_t drow = (size_t)t * DIM;
    for (int c = threadIdx.x; c < DIM; c += blockDim.x)
        x1[drow + c] = xt[drow + c] + proj[srow + c];
}

// ---------------- fused windowed attention ------------------------------------
__device__ __forceinline__ int region64(int v) { return v < 56 ? 0 : (v < 60 ? 1 : 2); }

__global__ __launch_bounds__(256) void attn_kernel(const float* __restrict__ qkv,
                                                   const float* __restrict__ rel_bias,
                                                   __half* __restrict__ out) {
    __shared__ float Qs[32][64];
    __shared__ float Ks[32][64];
    __shared__ float Vs[64][32];
    __shared__ float S[64][65];

    int blk = blockIdx.x;
    int win = blk / HEADS;
    int head = blk - win * HEADS;
    int tid = threadIdx.x;

    const float* base = qkv + (size_t)win * 64 * QKV_N + head * HEAD_DIM;
    {
        int n = tid >> 2;
        int d0 = (tid & 3) << 3;
        const float* qrow = base + (size_t)n * QKV_N;
        float4 q0 = *(const float4*)(qrow + d0);
        float4 q1 = *(const float4*)(qrow + d0 + 4);
        Qs[d0 + 0][n] = q0.x; Qs[d0 + 1][n] = q0.y; Qs[d0 + 2][n] = q0.z; Qs[d0 + 3][n] = q0.w;
        Qs[d0 + 4][n] = q1.x; Qs[d0 + 5][n] = q1.y; Qs[d0 + 6][n] = q1.z; Qs[d0 + 7][n] = q1.w;
        float4 k0 = *(const float4*)(qrow + DIM + d0);
        float4 k1 = *(const float4*)(qrow + DIM + d0 + 4);
        Ks[d0 + 0][n] = k0.x; Ks[d0 + 1][n] = k0.y; Ks[d0 + 2][n] = k0.z; Ks[d0 + 3][n] = k0.w;
        Ks[d0 + 4][n] = k1.x; Ks[d0 + 5][n] = k1.y; Ks[d0 + 6][n] = k1.z; Ks[d0 + 7][n] = k1.w;
        float4 v0 = *(const float4*)(qrow + 2 * DIM + d0);
        float4 v1 = *(const float4*)(qrow + 2 * DIM + d0 + 4);
        *(float4*)&Vs[n][d0] = v0;
        *(float4*)&Vs[n][d0 + 4] = v1;
    }
    __syncthreads();

    int mr = (tid >> 4) << 2;
    int nc = (tid & 15) << 2;
    float acc[4][4] = {};
#pragma unroll
    for (int d = 0; d < 32; d++) {
        float a[4], bfr[4];
        *(float4*)a = *(const float4*)&Qs[d][mr];
        *(float4*)bfr = *(const float4*)&Ks[d][nc];
#pragma unroll
        for (int i = 0; i < 4; i++)
#pragma unroll
            for (int j = 0; j < 4; j++) acc[i][j] += a[i] * bfr[j];
    }
    int win_img = win & 63;
    int wy = win_img >> 3, wx = win_img & 7;
#pragma unroll
    for (int i = 0; i < 4; i++) {
        int r = mr + i;
        int ry = r >> 3, rx = r & 7;
        int reg_r = region64(wy * 8 + ry) * 3 + region64(wx * 8 + rx);
#pragma unroll
        for (int j = 0; j < 4; j++) {
            int c = nc + j;
            int cy = c >> 3, cx = c & 7;
            int idx = (ry - cy + 7) * 15 + (rx - cx + 7);
            float bb = rel_bias[idx * HEADS + head];
            int reg_c = region64(wy * 8 + cy) * 3 + region64(wx * 8 + cx);
            float m = (reg_r != reg_c) ? -10.0f : 0.0f;
            S[r][c] = acc[i][j] * ATT_SCALE + bb + m;
        }
    }
    __syncthreads();

    int wid = tid >> 5, lane = tid & 31;
    for (int r = wid; r < 64; r += 8) {
        float v0 = S[r][lane], v1 = S[r][lane + 32];
        float mx = fmaxf(v0, v1);
#pragma unroll
        for (int o = 16; o; o >>= 1) mx = fmaxf(mx, __shfl_xor_sync(0xffffffffu, mx, o));
        float e0 = expf(v0 - mx), e1 = expf(v1 - mx);
        float sm = e0 + e1;
#pragma unroll
        for (int o = 16; o; o >>= 1) sm += __shfl_xor_sync(0xffffffffu, sm, o);
        float inv = 1.f / sm;
        S[r][lane] = e0 * inv;
        S[r][lane + 32] = e1 * inv;
    }
    __syncthreads();

    int r2 = (tid >> 3) << 1;
    int c2 = (tid & 7) << 2;
    float o0[4] = {}, o1[4] = {};
#pragma unroll
    for (int m = 0; m < 64; m++) {
        float s0 = S[r2][m], s1 = S[r2 + 1][m];
        float4 vv = *(const float4*)&Vs[m][c2];
        o0[0] += s0 * vv.x; o0[1] += s0 * vv.y; o0[2] += s0 * vv.z; o0[3] += s0 * vv.w;
        o1[0] += s1 * vv.x; o1[1] += s1 * vv.y; o1[2] += s1 * vv.z; o1[3] += s1 * vv.w;
    }
    __half* optr = out + ((size_t)(win * 64 + r2)) * DIM + head * HEAD_DIM + c2;
    *(__half2*)optr = __halves2half2(__float2half_rn(o0[0]), __float2half_rn(o0[1]));
    *(__half2*)(optr + 2) = __halves2half2(__float2half_rn(o0[2]), __float2half_rn(o0[3]));
    *(__half2*)(optr + DIM) = __halves2half2(__float2half_rn(o1[0]), __float2half_rn(o1[1]));
    *(__half2*)(optr + DIM + 2) = __halves2half2(__float2half_rn(o1[2]), __float2half_rn(o1[3]));
}

// ================= fp16 tensor-core GEMM (m16n8k16 mma.sync) =================
// C[M,N] = A[M,K] (half, row-major) * Bt[N,K]^T (half) + bias.
// Block 128x128, BK=32 halfs, 8 warps (4m x 2n), warp tile 32x64.
// MODE 0: float out.  MODE 1: GELU, half out.  MODE 2: +res, float out.
#define BKH 32
#define SA 40   // half stride; word-bank = 20*grp + lig -> permutation, conflict-free
#define SB 40

template <int MODE>
__global__ __launch_bounds__(256, 2) void hgemm(const __half* __restrict__ A,
                                                const __half* __restrict__ Bt,
                                                const float* __restrict__ bias,
                                                const float* __restrict__ res,
                                                void* __restrict__ Cout,
                                                int M, int N, int K) {
    __shared__ __half As[2][128 * SA];
    __shared__ __half Bs[2][128 * SB];

    const int tid = threadIdx.x;
    const int lane = tid & 31;
    const int wid = tid >> 5;
    const int grp = lane >> 2;      // 0..7
    const int lig = lane & 3;       // 0..3
    const int wm = wid & 3;         // 0..3
    const int wn = wid >> 2;        // 0..1
    const int bm = blockIdx.y * 128;
    const int bn = blockIdx.x * 128;

    // loader geometry: 16B chunks; 4 chunks per 32-half row
    const int l_r = tid >> 2;          // 0..63 (+64)
    const int l_c = (tid & 3) << 3;    // 0,8,16,24 halfs

    float acc[2][8][4];
#pragma unroll
    for (int mt = 0; mt < 2; mt++)
#pragma unroll
        for (int nt = 0; nt < 8; nt++)
#pragma unroll
            for (int i = 0; i < 4; i++) acc[mt][nt][i] = 0.f;

    const int T = K / BKH;

    auto issue = [&](int kt, int buf) {
#pragma unroll
        for (int i = 0; i < 2; i++) {
            int r = l_r + 64 * i;
            const __half* g = A + (size_t)(bm + r) * K + kt + l_c;
            unsigned s = (unsigned)__cvta_generic_to_shared(&As[buf][r * SA + l_c]);
            asm volatile("cp.async.cg.shared.global [%0], [%1], 16;\n" :: "r"(s), "l"(g));
        }
#pragma unroll
        for (int i = 0; i < 2; i++) {
            int r = l_r + 64 * i;
            const __half* g = Bt + (size_t)(bn + r) * K + kt + l_c;
            unsigned s = (unsigned)__cvta_generic_to_shared(&Bs[buf][r * SB + l_c]);
            asm volatile("cp.async.cg.shared.global [%0], [%1], 16;\n" :: "r"(s), "l"(g));
        }
        asm volatile("cp.async.commit_group;\n");
    };

    issue(0, 0);

    for (int t = 0; t < T; t++) {
        if (t + 1 < T) {
            issue((t + 1) * BKH, (t + 1) & 1);
            asm volatile("cp.async.wait_group 1;\n");
        } else {
            asm volatile("cp.async.wait_group 0;\n");
        }
        __syncthreads();

        const __half* Ab = As[t & 1];
        const __half* Bb = Bs[t & 1];

#pragma unroll
        for (int kk = 0; kk < 2; kk++) {
            int k0 = kk * 16;
            unsigned af[2][4], bf[8][2];
#pragma unroll
            for (int mt = 0; mt < 2; mt++) {
                int rm = wm * 32 + mt * 16 + grp;
                af[mt][0] = *(const unsigned*)&Ab[rm * SA + k0 + 2 * lig];
                af[mt][1] = *(const unsigned*)&Ab[(rm + 8) * SA + k0 + 2 * lig];
                af[mt][2] = *(const unsigned*)&Ab[rm * SA + k0 + 2 * lig + 8];
                af[mt][3] = *(const unsigned*)&Ab[(rm + 8) * SA + k0 + 2 * lig + 8];
            }
#pragma unroll
            for (int nt = 0; nt < 8; nt++) {
                int cn = wn * 64 + nt * 8 + grp;
                bf[nt][0] = *(const unsigned*)&Bb[cn * SB + k0 + 2 * lig];
                bf[nt][1] = *(const unsigned*)&Bb[cn * SB + k0 + 2 * lig + 8];
            }
#pragma unroll
            for (int mt = 0; mt < 2; mt++)
#pragma unroll
                for (int nt = 0; nt < 8; nt++) {
                    asm volatile(
                        "mma.sync.aligned.m16n8k16.row.col.f32.f16.f16.f32 "
                        "{%0,%1,%2,%3}, {%4,%5,%6,%7}, {%8,%9}, {%0,%1,%2,%3};\n"
                        : "+f"(acc[mt][nt][0]), "+f"(acc[mt][nt][1]),
                          "+f"(acc[mt][nt][2]), "+f"(acc[mt][nt][3])
                        : "r"(af[mt][0]), "r"(af[mt][1]), "r"(af[mt][2]), "r"(af[mt][3]),
                          "r"(bf[nt][0]), "r"(bf[nt][1]));
                }
        }
        __syncthreads();
    }

    // epilogue: c0:(grp,2l) c1:(grp,2l+1) c2:(grp+8,2l) c3:(grp+8,2l+1)
#pragma unroll
    for (int mt = 0; mt < 2; mt++) {
#pragma unroll
        for (int half_ = 0; half_ < 2; half_++) {
            int m = bm + wm * 32 + mt * 16 + grp + half_ * 8;
            size_t crow = (size_t)m * N;
#pragma unroll
            for (int nt = 0; nt < 8; nt++) {
                int n = bn + wn * 64 + nt * 8 + lig * 2;
                float v0 = acc[mt][nt][half_ * 2 + 0] + bias[n];
                float v1 = acc[mt][nt][half_ * 2 + 1] + bias[n + 1];
                if (MODE == 1) {
                    v0 = 0.5f * v0 * (1.0f + erff(v0 * 0.7071067811865476f));
                    v1 = 0.5f * v1 * (1.0f + erff(v1 * 0.7071067811865476f));
                    *(__half2*)((__half*)Cout + crow + n) =
                        __halves2half2(__float2half_rn(v0), __float2half_rn(v1));
                } else if (MODE == 2) {
                    v0 += res[(size_t)m * DIM + n];
                    v1 += res[(size_t)m * DIM + n + 1];
                    *(float2*)((float*)Cout + crow + n) = make_float2(v0, v1);
                } else {
                    *(float2*)((float*)Cout + crow + n) = make_float2(v0, v1);
                }
            }
        }
    }
}

// ---------------- launcher -----------------------------------------------------
extern "C" void kernel_launch(void* const* d_in, const int* in_sizes, int n_in,
                              void* d_out, int out_size) {
    const float* x       = (const float*)d_in[0];
    const float* qkv_w   = (const float*)d_in[1];
    const float* qkv_b   = (const float*)d_in[2];
    const float* proj_w  = (const float*)d_in[3];
    const float* proj_b  = (const float*)d_in[4];
    const float* rel_bias= (const float*)d_in[5];
    const float* norm1_g = (const float*)d_in[6];
    const float* norm1_b = (const float*)d_in[7];
    const float* norm2_g = (const float*)d_in[8];
    const float* norm2_b = (const float*)d_in[9];
    const float* fc1_w   = (const float*)d_in[10];
    const float* fc1_b   = (const float*)d_in[11];
    const float* fc2_w   = (const float*)d_in[12];
    const float* fc2_b   = (const float*)d_in[13];

    float *xt, *qkv, *proj, *x1;
    __half *xw, *attout, *h, *wt_qkv, *wt_proj, *wt_fc1, *wt_fc2;
    cudaGetSymbolAddress((void**)&xt, g_xt);
    cudaGetSymbolAddress((void**)&xw, g_xw);
    cudaGetSymbolAddress((void**)&qkv, g_qkv);
    cudaGetSymbolAddress((void**)&attout, g_attout);
    cudaGetSymbolAddress((void**)&proj, g_proj);
    cudaGetSymbolAddress((void**)&x1, g_x1);
    cudaGetSymbolAddress((void**)&h, g_h);
    cudaGetSymbolAddress((void**)&wt_qkv, g_wt_qkv);
    cudaGetSymbolAddress((void**)&wt_proj, g_wt_proj);
    cudaGetSymbolAddress((void**)&wt_fc1, g_wt_fc1);
    cudaGetSymbolAddress((void**)&wt_fc2, g_wt_fc2);

    // 0. weight transposes (K,N)->(N,K), fp16
    transpose_w<<<dim3(QKV_N / 32, DIM / 32), dim3(32, 8)>>>(qkv_w, wt_qkv, DIM, QKV_N);
    transpose_w<<<dim3(DIM / 32, DIM / 32), dim3(32, 8)>>>(proj_w, wt_proj, DIM, DIM);
    transpose_w<<<dim3(MLP_HIDDEN / 32, DIM / 32), dim3(32, 8)>>>(fc1_w, wt_fc1, DIM, MLP_HIDDEN);
    transpose_w<<<dim3(DIM / 32, MLP_HIDDEN / 32), dim3(32, 8)>>>(fc2_w, wt_fc2, MLP_HIDDEN, DIM);

    // 1. BCHW -> token-major (shortcut)
    transpose_in<<<dim3(128, 12, 32), dim3(32, 8)>>>(x, xt);
    // 2. LN1 + shift + window partition -> fp16
    ln_kernel<true><<<NTOK / 8, 256>>>(xt, norm1_g, norm1_b, xw);
    // 3. QKV projection (fp16 mma)
    hgemm<0><<<dim3(QKV_N / 128, NTOK / 128), 256>>>(xw, wt_qkv, qkv_b, nullptr, qkv,
                                                     NTOK, QKV_N, DIM);
    // 4. windowed attention -> fp16 out
    attn_kernel<<<2048 * HEADS, 256>>>(qkv, rel_bias, attout);
    // 5. output projection
    hgemm<0><<<dim3(DIM / 128, NTOK / 128), 256>>>(attout, wt_proj, proj_b, nullptr, proj,
                                                   NTOK, DIM, DIM);
    // 6. window reverse + unshift + residual
    resid_reverse<<<NTOK, 128>>>(xt, proj, x1);
    // 7. LN2 -> fp16
    ln_kernel<false><<<NTOK / 8, 256>>>(x1, norm2_g, norm2_b, xw);
    // 8. FC1 + GELU -> fp16
    hgemm<1><<<dim3(MLP_HIDDEN / 128, NTOK / 128), 256>>>(xw, wt_fc1, fc1_b, nullptr, h,
                                                          NTOK, MLP_HIDDEN, DIM);
    // 9. FC2 + residual -> float (reuse proj buffer)
    hgemm<2><<<dim3(DIM / 128, NTOK / 128), 256>>>(h, wt_fc2, fc2_b, x1, proj,
                                                   NTOK, DIM, MLP_HIDDEN);
    // 10. token-major -> BCHW
    transpose_out<<<dim3(128, 12, 32), dim3(32, 8)>>>(proj, (float*)d_out);
}

// round 6
// speedup vs baseline: 5.0543x; 1.2395x over previous
#include <cuda_runtime.h>
#include <cuda_fp16.h>
#include <cstdint>
#include <math.h>

#define DIM 384
#define HEADS 12
#define HEAD_DIM 32
#define NTOK 131072          // 32*64*64 tokens
#define QKV_N 1152
#define MLP_HIDDEN 1536
#define ATT_SCALE 0.17677669529663687f   // 32^-0.5

// ---------------- scratch (static device globals; no allocations) -------------
__device__ float  g_xt[NTOK * DIM];           // token-major input (shortcut)
__device__ __half g_xw[NTOK * DIM];           // LN output (GEMM A input)
__device__ __half g_qkv[NTOK * QKV_N];        // qkv projections (half)
__device__ __half g_attout[NTOK * DIM];       // attention output (GEMM A input)
__device__ float  g_fc2o[NTOK * DIM];         // FC2 output (token order)
__device__ float  g_x1[NTOK * DIM];           // post-attention residual
__device__ __half g_h[NTOK * MLP_HIDDEN];     // MLP hidden (GEMM A input)
// transposed (N,K) weights in fp16
__device__ __half g_wt_qkv[QKV_N * DIM];
__device__ __half g_wt_proj[DIM * DIM];
__device__ __half g_wt_fc1[MLP_HIDDEN * DIM];
__device__ __half g_wt_fc2[DIM * MLP_HIDDEN];

// ---------------- transpose: (B,C,HW) -> (B,HW,C) ----------------------------
__global__ void transpose_in(const float* __restrict__ x, float* __restrict__ xt) {
    __shared__ float tile[32][33];
    int b = blockIdx.z;
    int c0 = blockIdx.y * 32;
    int p0 = blockIdx.x * 32;
    const float* xb = x + (size_t)b * DIM * 4096;
    float* xtb = xt + (size_t)b * 4096 * DIM;
    int tx = threadIdx.x, ty = threadIdx.y;
#pragma unroll
    for (int i = 0; i < 32; i += 8)
        tile[ty + i][tx] = xb[(size_t)(c0 + ty + i) * 4096 + p0 + tx];
    __syncthreads();
#pragma unroll
    for (int i = 0; i < 32; i += 8)
        xtb[(size_t)(p0 + ty + i) * DIM + c0 + tx] = tile[tx][ty + i];
}

__global__ void transpose_out(const float* __restrict__ xt, float* __restrict__ y) {
    __shared__ float tile[32][33];
    int b = blockIdx.z;
    int c0 = blockIdx.y * 32;
    int p0 = blockIdx.x * 32;
    const float* xb = xt + (size_t)b * 4096 * DIM;
    float* yb = y + (size_t)b * DIM * 4096;
    int tx = threadIdx.x, ty = threadIdx.y;
#pragma unroll
    for (int i = 0; i < 32; i += 8)
        tile[ty + i][tx] = xb[(size_t)(p0 + ty + i) * DIM + c0 + tx];
    __syncthreads();
#pragma unroll
    for (int i = 0; i < 32; i += 8)
        yb[(size_t)(c0 + ty + i) * 4096 + p0 + tx] = tile[tx][ty + i];
}

// ---------------- weight transpose (K,N)->(N,K) fp16 -------------------------
__global__ void transpose_w(const float* __restrict__ W, __half* __restrict__ Wt,
                            int K, int N) {
    __shared__ float tile[32][33];
    int k0 = blockIdx.y * 32;
    int n0 = blockIdx.x * 32;
    int tx = threadIdx.x, ty = threadIdx.y;
#pragma unroll
    for (int i = 0; i < 32; i += 8)
        tile[ty + i][tx] = W[(size_t)(k0 + ty + i) * N + n0 + tx];
    __syncthreads();
#pragma unroll
    for (int i = 0; i < 32; i += 8)
        Wt[(size_t)(n0 + ty + i) * K + k0 + tx] = __float2half_rn(tile[tx][ty + i]);
}

// ---------------- LayerNorm (+optional shift+window gather) ------------------
template <bool WINDOWED>
__global__ void ln_kernel(const float* __restrict__ src,
                          const float* __restrict__ gamma,
                          const float* __restrict__ beta,
                          __half* __restrict__ dst) {
    int warp = (blockIdx.x * blockDim.x + threadIdx.x) >> 5;
    int lane = threadIdx.x & 31;
    if (warp >= NTOK) return;

    size_t srow;
    if (WINDOWED) {
        int pos = warp & 63;
        int win = (warp >> 6) & 63;
        int b = warp >> 12;
        int iy = pos >> 3, ix = pos & 7;
        int wy = win >> 3, wx = win & 7;
        int hs = (wy * 8 + iy + 4) & 63;   // roll(-4)
        int ws = (wx * 8 + ix + 4) & 63;
        srow = ((size_t)b * 4096 + hs * 64 + ws) * DIM;
    } else {
        srow = (size_t)warp * DIM;
    }
    const float* row = src + srow;

    float vals[12];
    float s = 0.f;
#pragma unroll
    for (int k = 0; k < 12; k++) { vals[k] = row[lane + k * 32]; s += vals[k]; }
#pragma unroll
    for (int o = 16; o; o >>= 1) s += __shfl_xor_sync(0xffffffffu, s, o);
    float mu = s * (1.f / 384.f);
    float vv = 0.f;
#pragma unroll
    for (int k = 0; k < 12; k++) { float d = vals[k] - mu; vv += d * d; }
#pragma unroll
    for (int o = 16; o; o >>= 1) vv += __shfl_xor_sync(0xffffffffu, vv, o);
    float rstd = rsqrtf(vv * (1.f / 384.f) + 1e-5f);

    __half* orow = dst + (size_t)warp * DIM;
#pragma unroll
    for (int k = 0; k < 12; k++) {
        int c = lane + k * 32;
        orow[c] = __float2half_rn((vals[k] - mu) * rstd * gamma[c] + beta[c]);
    }
}

// ---------------- fused windowed attention (fp16 mma) ------------------------
__device__ __forceinline__ int region64(int v) { return v < 56 ? 0 : (v < 60 ? 1 : 2); }

__device__ __forceinline__ unsigned pkh2(float a, float b) {
    __half2 h = __floats2half2_rn(a, b);
    return *(unsigned*)&h;
}

#define LDSM_X4(r0, r1, r2, r3, addr) \
    asm volatile("ldmatrix.sync.aligned.m8n8.x4.shared.b16 {%0,%1,%2,%3}, [%4];" \
                 : "=r"(r0), "=r"(r1), "=r"(r2), "=r"(r3) : "r"(addr))
#define LDSM_X4_T(r0, r1, r2, r3, addr) \
    asm volatile("ldmatrix.sync.aligned.m8n8.x4.trans.shared.b16 {%0,%1,%2,%3}, [%4];" \
                 : "=r"(r0), "=r"(r1), "=r"(r2), "=r"(r3) : "r"(addr))
#define MMA16816(d, a0, a1, a2, a3, b0, b1) \
    asm volatile("mma.sync.aligned.m16n8k16.row.col.f32.f16.f16.f32 " \
                 "{%0,%1,%2,%3}, {%4,%5,%6,%7}, {%8,%9}, {%0,%1,%2,%3};" \
                 : "+f"((d)[0]), "+f"((d)[1]), "+f"((d)[2]), "+f"((d)[3]) \
                 : "r"(a0), "r"(a1), "r"(a2), "r"(a3), "r"(b0), "r"(b1))

#define ASTRIDE 40   // halfs per row: conflict-free for ldmatrix

__global__ __launch_bounds__(128) void attn_mma(const __half* __restrict__ qkv,
                                                const float* __restrict__ rel_bias,
                                                __half* __restrict__ out) {
    __shared__ __half Qs[64 * ASTRIDE];
    __shared__ __half Ks[64 * ASTRIDE];
    __shared__ __half Vs[64 * ASTRIDE];
    __shared__ float sbias[225];

    int blk = blockIdx.x;
    int win = blk / HEADS;
    int head = blk - win * HEADS;
    int tid = threadIdx.x;
    int lane = tid & 31, warp = tid >> 5;
    int grp = lane >> 2, lig = lane & 3;

    for (int i = tid; i < 225; i += 128) sbias[i] = rel_bias[i * HEADS + head];

    {   // stage Q,K,V: thread -> row tid>>1, 16-half segment tid&1
        int n = tid >> 1;
        int c0 = (tid & 1) << 4;
        const __half* rowp = qkv + (size_t)(win * 64 + n) * QKV_N + head * HEAD_DIM + c0;
        *(uint4*)&Qs[n * ASTRIDE + c0]     = *(const uint4*)(rowp);
        *(uint4*)&Qs[n * ASTRIDE + c0 + 8] = *(const uint4*)(rowp + 8);
        *(uint4*)&Ks[n * ASTRIDE + c0]     = *(const uint4*)(rowp + DIM);
        *(uint4*)&Ks[n * ASTRIDE + c0 + 8] = *(const uint4*)(rowp + DIM + 8);
        *(uint4*)&Vs[n * ASTRIDE + c0]     = *(const uint4*)(rowp + 2 * DIM);
        *(uint4*)&Vs[n * ASTRIDE + c0 + 8] = *(const uint4*)(rowp + 2 * DIM + 8);
    }
    __syncthreads();

    const unsigned qb = (unsigned)__cvta_generic_to_shared(Qs);
    const unsigned kb = (unsigned)__cvta_generic_to_shared(Ks);
    const unsigned vb = (unsigned)__cvta_generic_to_shared(Vs);
    const int g = lane >> 3, j = lane & 7;

    // ---- A fragments for Q (rows warp*16..+15, k=0..31) ----
    unsigned qa[2][4];
#pragma unroll
    for (int kc = 0; kc < 2; kc++) {
        int row = warp * 16 + (g & 1) * 8 + j;
        int col = kc * 16 + (g >> 1) * 8;
        LDSM_X4(qa[kc][0], qa[kc][1], qa[kc][2], qa[kc][3],
                qb + (unsigned)((row * ASTRIDE + col) * 2));
    }

    // ---- S = Q @ K^T ----
    float sacc[8][4];
#pragma unroll
    for (int nt = 0; nt < 8; nt++)
#pragma unroll
        for (int i = 0; i < 4; i++) sacc[nt][i] = 0.f;

#pragma unroll
    for (int kc = 0; kc < 2; kc++) {
#pragma unroll
        for (int p = 0; p < 4; p++) {
            unsigned kf[4];
            int row = p * 16 + (g >> 1) * 8 + j;
            int col = kc * 16 + (g & 1) * 8;
            LDSM_X4(kf[0], kf[1], kf[2], kf[3],
                    kb + (unsigned)((row * ASTRIDE + col) * 2));
            MMA16816(sacc[2 * p],     qa[kc][0], qa[kc][1], qa[kc][2], qa[kc][3], kf[0], kf[1]);
            MMA16816(sacc[2 * p + 1], qa[kc][0], qa[kc][1], qa[kc][2], qa[kc][3], kf[2], kf[3]);
        }
    }

    // ---- bias + mask + softmax in registers ----
    int win_img = win & 63;
    int wy = win_img >> 3, wx = win_img & 7;
    int r_lo = warp * 16 + grp, r_hi = r_lo + 8;
    int ry_lo = r_lo >> 3, rx = r_lo & 7;      // rx same for hi (row+8 => ry+1)
    int ry_hi = r_hi >> 3;
    int reg_lo = region64(wy * 8 + ry_lo) * 3 + region64(wx * 8 + rx);
    int reg_hi = region64(wy * 8 + ry_hi) * 3 + region64(wx * 8 + rx);

    float mx_lo = -1e30f, mx_hi = -1e30f;
#pragma unroll
    for (int nt = 0; nt < 8; nt++) {
#pragma unroll
        for (int jj = 0; jj < 2; jj++) {
            int c = nt * 8 + 2 * lig + jj;
            int cy = c >> 3, cx = c & 7;
            int regc = region64(wy * 8 + cy) * 3 + region64(wx * 8 + cx);
            float blo = sbias[(ry_lo - cy + 7) * 15 + (rx - cx + 7)];
            float bhi = sbias[(ry_hi - cy + 7) * 15 + (rx - cx + 7)];
            float vlo = sacc[nt][jj] * ATT_SCALE + blo + (reg_lo != regc ? -10.f : 0.f);
            float vhi = sacc[nt][2 + jj] * ATT_SCALE + bhi + (reg_hi != regc ? -10.f : 0.f);
            sacc[nt][jj] = vlo;
            sacc[nt][2 + jj] = vhi;
            mx_lo = fmaxf(mx_lo, vlo);
            mx_hi = fmaxf(mx_hi, vhi);
        }
    }
    mx_lo = fmaxf(mx_lo, __shfl_xor_sync(0xffffffffu, mx_lo, 1));
    mx_lo = fmaxf(mx_lo, __shfl_xor_sync(0xffffffffu, mx_lo, 2));
    mx_hi = fmaxf(mx_hi, __shfl_xor_sync(0xffffffffu, mx_hi, 1));
    mx_hi = fmaxf(mx_hi, __shfl_xor_sync(0xffffffffu, mx_hi, 2));

    float sm_lo = 0.f, sm_hi = 0.f;
#pragma unroll
    for (int nt = 0; nt < 8; nt++) {
#pragma unroll
        for (int jj = 0; jj < 2; jj++) {
            float elo = __expf(sacc[nt][jj] - mx_lo);
            float ehi = __expf(sacc[nt][2 + jj] - mx_hi);
            sacc[nt][jj] = elo;
            sacc[nt][2 + jj] = ehi;
            sm_lo += elo;
            sm_hi += ehi;
        }
    }
    sm_lo += __shfl_xor_sync(0xffffffffu, sm_lo, 1);
    sm_lo += __shfl_xor_sync(0xffffffffu, sm_lo, 2);
    sm_hi += __shfl_xor_sync(0xffffffffu, sm_hi, 1);
    sm_hi += __shfl_xor_sync(0xffffffffu, sm_hi, 2);
    float inv_lo = 1.f / sm_lo, inv_hi = 1.f / sm_hi;

    // ---- O = P @ V ----
    float oacc[4][4];
#pragma unroll
    for (int nt = 0; nt < 4; nt++)
#pragma unroll
        for (int i = 0; i < 4; i++) oacc[nt][i] = 0.f;

#pragma unroll
    for (int kc = 0; kc < 4; kc++) {
        unsigned pa[4];
        pa[0] = pkh2(sacc[2 * kc][0] * inv_lo,     sacc[2 * kc][1] * inv_lo);
        pa[1] = pkh2(sacc[2 * kc][2] * inv_hi,     sacc[2 * kc][3] * inv_hi);
        pa[2] = pkh2(sacc[2 * kc + 1][0] * inv_lo, sacc[2 * kc + 1][1] * inv_lo);
        pa[3] = pkh2(sacc[2 * kc + 1][2] * inv_hi, sacc[2 * kc + 1][3] * inv_hi);
#pragma unroll
        for (int q = 0; q < 2; q++) {
            unsigned vf[4];
            int row = kc * 16 + (g & 1) * 8 + j;
            int col = q * 16 + (g >> 1) * 8;
            LDSM_X4_T(vf[0], vf[1], vf[2], vf[3],
                      vb + (unsigned)((row * ASTRIDE + col) * 2));
            MMA16816(oacc[2 * q],     pa[0], pa[1], pa[2], pa[3], vf[0], vf[1]);
            MMA16816(oacc[2 * q + 1], pa[0], pa[1], pa[2], pa[3], vf[2], vf[3]);
        }
    }

    // ---- write O (half) ----
#pragma unroll
    for (int nt = 0; nt < 4; nt++) {
        int col = head * HEAD_DIM + nt * 8 + 2 * lig;
        __half2 lo = __floats2half2_rn(oacc[nt][0], oacc[nt][1]);
        __half2 hi = __floats2half2_rn(oacc[nt][2], oacc[nt][3]);
        *(__half2*)&out[(size_t)(win * 64 + r_lo) * DIM + col] = lo;
        *(__half2*)&out[(size_t)(win * 64 + r_hi) * DIM + col] = hi;
    }
}

// ================= fp16 tensor-core GEMM (m16n8k16 mma.sync) =================
// C[M,N] = A[M,K] (half, row-major) * Bt[N,K]^T (half) + bias.
// Block 128x128, BK=32 halfs, 8 warps (4m x 2n), warp tile 32x64.
// MODE 0: half out. MODE 1: GELU, half out. MODE 2: +res, float out.
// MODE 3: window-reverse+unshift residual (+res at token t), float out.
#define BKH 32
#define SA 40
#define SB 40

template <int MODE>
__global__ __launch_bounds__(256, 2) void hgemm(const __half* __restrict__ A,
                                                const __half* __restrict__ Bt,
                                                const float* __restrict__ bias,
                                                const float* __restrict__ res,
                                                void* __restrict__ Cout,
                                                int M, int N, int K) {
    __shared__ __half As[2][128 * SA];
    __shared__ __half Bs[2][128 * SB];

    const int tid = threadIdx.x;
    const int lane = tid & 31;
    const int wid = tid >> 5;
    const int grp = lane >> 2;
    const int lig = lane & 3;
    const int wm = wid & 3;
    const int wn = wid >> 2;
    const int bm = blockIdx.y * 128;
    const int bn = blockIdx.x * 128;

    const int l_r = tid >> 2;
    const int l_c = (tid & 3) << 3;

    float acc[2][8][4];
#pragma unroll
    for (int mt = 0; mt < 2; mt++)
#pragma unroll
        for (int nt = 0; nt < 8; nt++)
#pragma unroll
            for (int i = 0; i < 4; i++) acc[mt][nt][i] = 0.f;

    const int T = K / BKH;

    auto issue = [&](int kt, int buf) {
#pragma unroll
        for (int i = 0; i < 2; i++) {
            int r = l_r + 64 * i;
            const __half* gp = A + (size_t)(bm + r) * K + kt + l_c;
            unsigned s = (unsigned)__cvta_generic_to_shared(&As[buf][r * SA + l_c]);
            asm volatile("cp.async.cg.shared.global [%0], [%1], 16;\n" :: "r"(s), "l"(gp));
        }
#pragma unroll
        for (int i = 0; i < 2; i++) {
            int r = l_r + 64 * i;
            const __half* gp = Bt + (size_t)(bn + r) * K + kt + l_c;
            unsigned s = (unsigned)__cvta_generic_to_shared(&Bs[buf][r * SB + l_c]);
            asm volatile("cp.async.cg.shared.global [%0], [%1], 16;\n" :: "r"(s), "l"(gp));
        }
        asm volatile("cp.async.commit_group;\n");
    };

    issue(0, 0);

    for (int t = 0; t < T; t++) {
        if (t + 1 < T) {
            issue((t + 1) * BKH, (t + 1) & 1);
            asm volatile("cp.async.wait_group 1;\n");
        } else {
            asm volatile("cp.async.wait_group 0;\n");
        }
        __syncthreads();

        const __half* Ab = As[t & 1];
        const __half* Bb = Bs[t & 1];

#pragma unroll
        for (int kk = 0; kk < 2; kk++) {
            int k0 = kk * 16;
            unsigned af[2][4], bf[8][2];
#pragma unroll
            for (int mt = 0; mt < 2; mt++) {
                int rm = wm * 32 + mt * 16 + grp;
                af[mt][0] = *(const unsigned*)&Ab[rm * SA + k0 + 2 * lig];
                af[mt][1] = *(const unsigned*)&Ab[(rm + 8) * SA + k0 + 2 * lig];
                af[mt][2] = *(const unsigned*)&Ab[rm * SA + k0 + 2 * lig + 8];
                af[mt][3] = *(const unsigned*)&Ab[(rm + 8) * SA + k0 + 2 * lig + 8];
            }
#pragma unroll
            for (int nt = 0; nt < 8; nt++) {
                int cn = wn * 64 + nt * 8 + grp;
                bf[nt][0] = *(const unsigned*)&Bb[cn * SB + k0 + 2 * lig];
                bf[nt][1] = *(const unsigned*)&Bb[cn * SB + k0 + 2 * lig + 8];
            }
#pragma unroll
            for (int mt = 0; mt < 2; mt++)
#pragma unroll
                for (int nt = 0; nt < 8; nt++)
                    MMA16816(acc[mt][nt], af[mt][0], af[mt][1], af[mt][2], af[mt][3],
                             bf[nt][0], bf[nt][1]);
        }
        __syncthreads();
    }

#pragma unroll
    for (int mt = 0; mt < 2; mt++) {
#pragma unroll
        for (int half_ = 0; half_ < 2; half_++) {
            int m = bm + wm * 32 + mt * 16 + grp + half_ * 8;
            size_t crow;
            size_t rrow = 0;
            if (MODE == 3) {
                int b = m >> 12, win = (m >> 6) & 63, pos = m & 63;
                int wy = win >> 3, wx = win & 7, iy = pos >> 3, ix = pos & 7;
                int h = (wy * 8 + iy + 4) & 63;
                int w = (wx * 8 + ix + 4) & 63;
                size_t tk = (size_t)b * 4096 + h * 64 + w;
                crow = tk * N;
                rrow = tk * DIM;
            } else {
                crow = (size_t)m * N;
                rrow = (size_t)m * DIM;
            }
#pragma unroll
            for (int nt = 0; nt < 8; nt++) {
                int n = bn + wn * 64 + nt * 8 + lig * 2;
                float v0 = acc[mt][nt][half_ * 2 + 0] + bias[n];
                float v1 = acc[mt][nt][half_ * 2 + 1] + bias[n + 1];
                if (MODE == 0) {
                    *(__half2*)((__half*)Cout + crow + n) = __floats2half2_rn(v0, v1);
                } else if (MODE == 1) {
                    v0 = 0.5f * v0 * (1.0f + erff(v0 * 0.7071067811865476f));
                    v1 = 0.5f * v1 * (1.0f + erff(v1 * 0.7071067811865476f));
                    *(__half2*)((__half*)Cout + crow + n) = __floats2half2_rn(v0, v1);
                } else {  // MODE 2, 3: + residual, float out
                    v0 += res[rrow + n];
                    v1 += res[rrow + n + 1];
                    *(float2*)((float*)Cout + crow + n) = make_float2(v0, v1);
                }
            }
        }
    }
}

// ---------------- launcher -----------------------------------------------------
extern "C" void kernel_launch(void* const* d_in, const int* in_sizes, int n_in,
                              void* d_out, int out_size) {
    const float* x       = (const float*)d_in[0];
    const float* qkv_w   = (const float*)d_in[1];
    const float* qkv_b   = (const float*)d_in[2];
    const float* proj_w  = (const float*)d_in[3];
    const float* proj_b  = (const float*)d_in[4];
    const float* rel_bias= (const float*)d_in[5];
    const float* norm1_g = (const float*)d_in[6];
    const float* norm1_b = (const float*)d_in[7];
    const float* norm2_g = (const float*)d_in[8];
    const float* norm2_b = (const float*)d_in[9];
    const float* fc1_w   = (const float*)d_in[10];
    const float* fc1_b   = (const float*)d_in[11];
    const float* fc2_w   = (const float*)d_in[12];
    const float* fc2_b   = (const float*)d_in[13];

    float *xt, *fc2o, *x1;
    __half *xw, *qkv, *attout, *h, *wt_qkv, *wt_proj, *wt_fc1, *wt_fc2;
    cudaGetSymbolAddress((void**)&xt, g_xt);
    cudaGetSymbolAddress((void**)&xw, g_xw);
    cudaGetSymbolAddress((void**)&qkv, g_qkv);
    cudaGetSymbolAddress((void**)&attout, g_attout);
    cudaGetSymbolAddress((void**)&fc2o, g_fc2o);
    cudaGetSymbolAddress((void**)&x1, g_x1);
    cudaGetSymbolAddress((void**)&h, g_h);
    cudaGetSymbolAddress((void**)&wt_qkv, g_wt_qkv);
    cudaGetSymbolAddress((void**)&wt_proj, g_wt_proj);
    cudaGetSymbolAddress((void**)&wt_fc1, g_wt_fc1);
    cudaGetSymbolAddress((void**)&wt_fc2, g_wt_fc2);

    // 0. weight transposes (K,N)->(N,K), fp16
    transpose_w<<<dim3(QKV_N / 32, DIM / 32), dim3(32, 8)>>>(qkv_w, wt_qkv, DIM, QKV_N);
    transpose_w<<<dim3(DIM / 32, DIM / 32), dim3(32, 8)>>>(proj_w, wt_proj, DIM, DIM);
    transpose_w<<<dim3(MLP_HIDDEN / 32, DIM / 32), dim3(32, 8)>>>(fc1_w, wt_fc1, DIM, MLP_HIDDEN);
    transpose_w<<<dim3(DIM / 32, MLP_HIDDEN / 32), dim3(32, 8)>>>(fc2_w, wt_fc2, MLP_HIDDEN, DIM);

    // 1. BCHW -> token-major (shortcut)
    transpose_in<<<dim3(128, 12, 32), dim3(32, 8)>>>(x, xt);
    // 2. LN1 + shift + window partition -> fp16
    ln_kernel<true><<<NTOK / 8, 256>>>(xt, norm1_g, norm1_b, xw);
    // 3. QKV projection -> half
    hgemm<0><<<dim3(QKV_N / 128, NTOK / 128), 256>>>(xw, wt_qkv, qkv_b, nullptr, qkv,
                                                     NTOK, QKV_N, DIM);
    // 4. windowed attention (fp16 mma, register softmax) -> half
    attn_mma<<<2048 * HEADS, 128>>>(qkv, rel_bias, attout);
    // 5. output projection + fused window-reverse/unshift + residual(xt) -> x1
    hgemm<3><<<dim3(DIM / 128, NTOK / 128), 256>>>(attout, wt_proj, proj_b, xt, x1,
                                                   NTOK, DIM, DIM);
    // 6. LN2 -> fp16
    ln_kernel<false><<<NTOK / 8, 256>>>(x1, norm2_g, norm2_b, xw);
    // 7. FC1 + GELU -> fp16
    hgemm<1><<<dim3(MLP_HIDDEN / 128, NTOK / 128), 256>>>(xw, wt_fc1, fc1_b, nullptr, h,
                                                          NTOK, MLP_HIDDEN, DIM);
    // 8. FC2 + residual(x1) -> float
    hgemm<2><<<dim3(DIM / 128, NTOK / 128), 256>>>(h, wt_fc2, fc2_b, x1, fc2o,
                                                   NTOK, DIM, MLP_HIDDEN);
    // 9. token-major -> BCHW
    transpose_out<<<dim3(128, 12, 32), dim3(32, 8)>>>(fc2o, (float*)d_out);
}

// round 7
// speedup vs baseline: 5.1445x; 1.0178x over previous
#include <cuda_runtime.h>
#include <cuda_fp16.h>
#include <cstdint>
#include <math.h>

#define DIM 384
#define HEADS 12
#define HEAD_DIM 32
#define NTOK 131072          // 32*64*64 tokens
#define QKV_N 1152
#define MLP_HIDDEN 1536
#define ATT_SCALE 0.17677669529663687f   // 32^-0.5

// ---------------- scratch (static device globals; no allocations) -------------
__device__ float  g_xt[NTOK * DIM];           // token-major input (shortcut)
__device__ __half g_xw[NTOK * DIM];           // LN output (GEMM A input)
__device__ __half g_qkv[NTOK * QKV_N];        // qkv projections (half)
__device__ __half g_attout[NTOK * DIM];       // attention output (GEMM A input)
__device__ float  g_x1[NTOK * DIM];           // post-attention residual
__device__ __half g_h[NTOK * MLP_HIDDEN];     // MLP hidden (GEMM A input)
// transposed (N,K) weights in fp16
__device__ __half g_wt_qkv[QKV_N * DIM];
__device__ __half g_wt_proj[DIM * DIM];
__device__ __half g_wt_fc1[MLP_HIDDEN * DIM];
__device__ __half g_wt_fc2[DIM * MLP_HIDDEN];

// ---------------- mma / ldmatrix helpers --------------------------------------
#define LDSM_X4(r0, r1, r2, r3, addr) \
    asm volatile("ldmatrix.sync.aligned.m8n8.x4.shared.b16 {%0,%1,%2,%3}, [%4];" \
                 : "=r"(r0), "=r"(r1), "=r"(r2), "=r"(r3) : "r"(addr))
#define LDSM_X4_T(r0, r1, r2, r3, addr) \
    asm volatile("ldmatrix.sync.aligned.m8n8.x4.trans.shared.b16 {%0,%1,%2,%3}, [%4];" \
                 : "=r"(r0), "=r"(r1), "=r"(r2), "=r"(r3) : "r"(addr))
#define MMA16816(d, a0, a1, a2, a3, b0, b1) \
    asm volatile("mma.sync.aligned.m16n8k16.row.col.f32.f16.f16.f32 " \
                 "{%0,%1,%2,%3}, {%4,%5,%6,%7}, {%8,%9}, {%0,%1,%2,%3};" \
                 : "+f"((d)[0]), "+f"((d)[1]), "+f"((d)[2]), "+f"((d)[3]) \
                 : "r"(a0), "r"(a1), "r"(a2), "r"(a3), "r"(b0), "r"(b1))

// ---------------- transpose: (B,C,HW) -> (B,HW,C) ----------------------------
__global__ void transpose_in(const float* __restrict__ x, float* __restrict__ xt) {
    __shared__ float tile[32][33];
    int b = blockIdx.z;
    int c0 = blockIdx.y * 32;
    int p0 = blockIdx.x * 32;
    const float* xb = x + (size_t)b * DIM * 4096;
    float* xtb = xt + (size_t)b * 4096 * DIM;
    int tx = threadIdx.x, ty = threadIdx.y;
#pragma unroll
    for (int i = 0; i < 32; i += 8)
        tile[ty + i][tx] = xb[(size_t)(c0 + ty + i) * 4096 + p0 + tx];
    __syncthreads();
#pragma unroll
    for (int i = 0; i < 32; i += 8)
        xtb[(size_t)(p0 + ty + i) * DIM + c0 + tx] = tile[tx][ty + i];
}

// ---------------- all 4 weight transposes in ONE launch -----------------------
__global__ void transpose_w4(const float* __restrict__ qkv_w, const float* __restrict__ proj_w,
                             const float* __restrict__ fc1_w, const float* __restrict__ fc2_w,
                             __half* __restrict__ wt_qkv, __half* __restrict__ wt_proj,
                             __half* __restrict__ wt_fc1, __half* __restrict__ wt_fc2) {
    __shared__ float tile[32][33];
    int z = blockIdx.z;
    const float* W;
    __half* Wt;
    int K, N;
    if (z == 0)      { W = qkv_w;  Wt = wt_qkv;  K = DIM;        N = QKV_N; }
    else if (z == 1) { W = proj_w; Wt = wt_proj; K = DIM;        N = DIM; }
    else if (z == 2) { W = fc1_w;  Wt = wt_fc1;  K = DIM;        N = MLP_HIDDEN; }
    else             { W = fc2_w;  Wt = wt_fc2;  K = MLP_HIDDEN; N = DIM; }
    int n0 = blockIdx.x * 32;
    int k0 = blockIdx.y * 32;
    if (n0 >= N || k0 >= K) return;
    int tx = threadIdx.x, ty = threadIdx.y;
#pragma unroll
    for (int i = 0; i < 32; i += 8)
        tile[ty + i][tx] = W[(size_t)(k0 + ty + i) * N + n0 + tx];
    __syncthreads();
#pragma unroll
    for (int i = 0; i < 32; i += 8)
        Wt[(size_t)(n0 + ty + i) * K + k0 + tx] = __float2half_rn(tile[tx][ty + i]);
}

// ---------------- LayerNorm (+optional shift+window gather) ------------------
template <bool WINDOWED>
__global__ void ln_kernel(const float* __restrict__ src,
                          const float* __restrict__ gamma,
                          const float* __restrict__ beta,
                          __half* __restrict__ dst) {
    int warp = (blockIdx.x * blockDim.x + threadIdx.x) >> 5;
    int lane = threadIdx.x & 31;
    if (warp >= NTOK) return;

    size_t srow;
    if (WINDOWED) {
        int pos = warp & 63;
        int win = (warp >> 6) & 63;
        int b = warp >> 12;
        int iy = pos >> 3, ix = pos & 7;
        int wy = win >> 3, wx = win & 7;
        int hs = (wy * 8 + iy + 4) & 63;   // roll(-4)
        int ws = (wx * 8 + ix + 4) & 63;
        srow = ((size_t)b * 4096 + hs * 64 + ws) * DIM;
    } else {
        srow = (size_t)warp * DIM;
    }
    const float* row = src + srow;

    float vals[12];
    float s = 0.f;
#pragma unroll
    for (int k = 0; k < 12; k++) { vals[k] = row[lane + k * 32]; s += vals[k]; }
#pragma unroll
    for (int o = 16; o; o >>= 1) s += __shfl_xor_sync(0xffffffffu, s, o);
    float mu = s * (1.f / 384.f);
    float vv = 0.f;
#pragma unroll
    for (int k = 0; k < 12; k++) { float d = vals[k] - mu; vv += d * d; }
#pragma unroll
    for (int o = 16; o; o >>= 1) vv += __shfl_xor_sync(0xffffffffu, vv, o);
    float rstd = rsqrtf(vv * (1.f / 384.f) + 1e-5f);

    __half* orow = dst + (size_t)warp * DIM;
#pragma unroll
    for (int k = 0; k < 12; k++) {
        int c = lane + k * 32;
        orow[c] = __float2half_rn((vals[k] - mu) * rstd * gamma[c] + beta[c]);
    }
}

// ---------------- fused windowed attention (fp16 mma) ------------------------
__device__ __forceinline__ int region64(int v) { return v < 56 ? 0 : (v < 60 ? 1 : 2); }

__device__ __forceinline__ unsigned pkh2(float a, float b) {
    __half2 h = __floats2half2_rn(a, b);
    return *(unsigned*)&h;
}

#define ASTRIDE 40   // halfs per row: conflict-free for ldmatrix

__global__ __launch_bounds__(128) void attn_mma(const __half* __restrict__ qkv,
                                                const float* __restrict__ rel_bias,
                                                __half* __restrict__ out) {
    __shared__ __half Qs[64 * ASTRIDE];
    __shared__ __half Ks[64 * ASTRIDE];
    __shared__ __half Vs[64 * ASTRIDE];
    __shared__ float sbias[225];

    int blk = blockIdx.x;
    int win = blk / HEADS;
    int head = blk - win * HEADS;
    int tid = threadIdx.x;
    int lane = tid & 31, warp = tid >> 5;
    int grp = lane >> 2, lig = lane & 3;

    for (int i = tid; i < 225; i += 128) sbias[i] = rel_bias[i * HEADS + head];

    {   // stage Q,K,V
        int n = tid >> 1;
        int c0 = (tid & 1) << 4;
        const __half* rowp = qkv + (size_t)(win * 64 + n) * QKV_N + head * HEAD_DIM + c0;
        *(uint4*)&Qs[n * ASTRIDE + c0]     = *(const uint4*)(rowp);
        *(uint4*)&Qs[n * ASTRIDE + c0 + 8] = *(const uint4*)(rowp + 8);
        *(uint4*)&Ks[n * ASTRIDE + c0]     = *(const uint4*)(rowp + DIM);
        *(uint4*)&Ks[n * ASTRIDE + c0 + 8] = *(const uint4*)(rowp + DIM + 8);
        *(uint4*)&Vs[n * ASTRIDE + c0]     = *(const uint4*)(rowp + 2 * DIM);
        *(uint4*)&Vs[n * ASTRIDE + c0 + 8] = *(const uint4*)(rowp + 2 * DIM + 8);
    }
    __syncthreads();

    const unsigned qb = (unsigned)__cvta_generic_to_shared(Qs);
    const unsigned kb = (unsigned)__cvta_generic_to_shared(Ks);
    const unsigned vb = (unsigned)__cvta_generic_to_shared(Vs);
    const int g = lane >> 3, j = lane & 7;

    unsigned qa[2][4];
#pragma unroll
    for (int kc = 0; kc < 2; kc++) {
        int row = warp * 16 + (g & 1) * 8 + j;
        int col = kc * 16 + (g >> 1) * 8;
        LDSM_X4(qa[kc][0], qa[kc][1], qa[kc][2], qa[kc][3],
                qb + (unsigned)((row * ASTRIDE + col) * 2));
    }

    float sacc[8][4];
#pragma unroll
    for (int nt = 0; nt < 8; nt++)
#pragma unroll
        for (int i = 0; i < 4; i++) sacc[nt][i] = 0.f;

#pragma unroll
    for (int kc = 0; kc < 2; kc++) {
#pragma unroll
        for (int p = 0; p < 4; p++) {
            unsigned kf[4];
            int row = p * 16 + (g >> 1) * 8 + j;
            int col = kc * 16 + (g & 1) * 8;
            LDSM_X4(kf[0], kf[1], kf[2], kf[3],
                    kb + (unsigned)((row * ASTRIDE + col) * 2));
            MMA16816(sacc[2 * p],     qa[kc][0], qa[kc][1], qa[kc][2], qa[kc][3], kf[0], kf[1]);
            MMA16816(sacc[2 * p + 1], qa[kc][0], qa[kc][1], qa[kc][2], qa[kc][3], kf[2], kf[3]);
        }
    }

    int win_img = win & 63;
    int wy = win_img >> 3, wx = win_img & 7;
    int r_lo = warp * 16 + grp, r_hi = r_lo + 8;
    int ry_lo = r_lo >> 3, rx = r_lo & 7;
    int ry_hi = r_hi >> 3;
    int reg_lo = region64(wy * 8 + ry_lo) * 3 + region64(wx * 8 + rx);
    int reg_hi = region64(wy * 8 + ry_hi) * 3 + region64(wx * 8 + rx);

    float mx_lo = -1e30f, mx_hi = -1e30f;
#pragma unroll
    for (int nt = 0; nt < 8; nt++) {
#pragma unroll
        for (int jj = 0; jj < 2; jj++) {
            int c = nt * 8 + 2 * lig + jj;
            int cy = c >> 3, cx = c & 7;
            int regc = region64(wy * 8 + cy) * 3 + region64(wx * 8 + cx);
            float blo = sbias[(ry_lo - cy + 7) * 15 + (rx - cx + 7)];
            float bhi = sbias[(ry_hi - cy + 7) * 15 + (rx - cx + 7)];
            float vlo = sacc[nt][jj] * ATT_SCALE + blo + (reg_lo != regc ? -10.f : 0.f);
            float vhi = sacc[nt][2 + jj] * ATT_SCALE + bhi + (reg_hi != regc ? -10.f : 0.f);
            sacc[nt][jj] = vlo;
            sacc[nt][2 + jj] = vhi;
            mx_lo = fmaxf(mx_lo, vlo);
            mx_hi = fmaxf(mx_hi, vhi);
        }
    }
    mx_lo = fmaxf(mx_lo, __shfl_xor_sync(0xffffffffu, mx_lo, 1));
    mx_lo = fmaxf(mx_lo, __shfl_xor_sync(0xffffffffu, mx_lo, 2));
    mx_hi = fmaxf(mx_hi, __shfl_xor_sync(0xffffffffu, mx_hi, 1));
    mx_hi = fmaxf(mx_hi, __shfl_xor_sync(0xffffffffu, mx_hi, 2));

    float sm_lo = 0.f, sm_hi = 0.f;
#pragma unroll
    for (int nt = 0; nt < 8; nt++) {
#pragma unroll
        for (int jj = 0; jj < 2; jj++) {
            float elo = __expf(sacc[nt][jj] - mx_lo);
            float ehi = __expf(sacc[nt][2 + jj] - mx_hi);
            sacc[nt][jj] = elo;
            sacc[nt][2 + jj] = ehi;
            sm_lo += elo;
            sm_hi += ehi;
        }
    }
    sm_lo += __shfl_xor_sync(0xffffffffu, sm_lo, 1);
    sm_lo += __shfl_xor_sync(0xffffffffu, sm_lo, 2);
    sm_hi += __shfl_xor_sync(0xffffffffu, sm_hi, 1);
    sm_hi += __shfl_xor_sync(0xffffffffu, sm_hi, 2);
    float inv_lo = 1.f / sm_lo, inv_hi = 1.f / sm_hi;

    float oacc[4][4];
#pragma unroll
    for (int nt = 0; nt < 4; nt++)
#pragma unroll
        for (int i = 0; i < 4; i++) oacc[nt][i] = 0.f;

#pragma unroll
    for (int kc = 0; kc < 4; kc++) {
        unsigned pa[4];
        pa[0] = pkh2(sacc[2 * kc][0] * inv_lo,     sacc[2 * kc][1] * inv_lo);
        pa[1] = pkh2(sacc[2 * kc][2] * inv_hi,     sacc[2 * kc][3] * inv_hi);
        pa[2] = pkh2(sacc[2 * kc + 1][0] * inv_lo, sacc[2 * kc + 1][1] * inv_lo);
        pa[3] = pkh2(sacc[2 * kc + 1][2] * inv_hi, sacc[2 * kc + 1][3] * inv_hi);
#pragma unroll
        for (int q = 0; q < 2; q++) {
            unsigned vf[4];
            int row = kc * 16 + (g & 1) * 8 + j;
            int col = q * 16 + (g >> 1) * 8;
            LDSM_X4_T(vf[0], vf[1], vf[2], vf[3],
                      vb + (unsigned)((row * ASTRIDE + col) * 2));
            MMA16816(oacc[2 * q],     pa[0], pa[1], pa[2], pa[3], vf[0], vf[1]);
            MMA16816(oacc[2 * q + 1], pa[0], pa[1], pa[2], pa[3], vf[2], vf[3]);
        }
    }

#pragma unroll
    for (int nt = 0; nt < 4; nt++) {
        int col = head * HEAD_DIM + nt * 8 + 2 * lig;
        __half2 lo = __floats2half2_rn(oacc[nt][0], oacc[nt][1]);
        __half2 hi = __floats2half2_rn(oacc[nt][2], oacc[nt][3]);
        *(__half2*)&out[(size_t)(win * 64 + r_lo) * DIM + col] = lo;
        *(__half2*)&out[(size_t)(win * 64 + r_hi) * DIM + col] = hi;
    }
}

// ================= fp16 tensor-core GEMM (m16n8k16 mma.sync) =================
// C[M,N] = A[M,K] (half) * Bt[N,K]^T (half) + bias.
// MODE 0: half out. MODE 1: GELU, half out.
// MODE 3: window-reverse+unshift residual, float out (token order).
// MODE 4: +res, write BCHW (transposed, smem-staged), float out = d_out.
#define BKH 32
#define SA 40
#define SB 40

template <int MODE>
__global__ __launch_bounds__(256, 2) void hgemm(const __half* __restrict__ A,
                                                const __half* __restrict__ Bt,
                                                const float* __restrict__ bias,
                                                const float* __restrict__ res,
                                                void* __restrict__ Cout,
                                                int M, int N, int K) {
    __shared__ __half As[2][128 * SA];
    __shared__ __half Bs[2][128 * SB];

    const int tid = threadIdx.x;
    const int lane = tid & 31;
    const int wid = tid >> 5;
    const int grp = lane >> 2;
    const int lig = lane & 3;
    const int g = lane >> 3;
    const int j = lane & 7;
    const int wm = wid & 3;
    const int wn = wid >> 2;
    const int bm = blockIdx.y * 128;
    const int bn = blockIdx.x * 128;

    const int l_r = tid >> 2;
    const int l_c = (tid & 3) << 3;

    float acc[2][8][4];
#pragma unroll
    for (int mt = 0; mt < 2; mt++)
#pragma unroll
        for (int nt = 0; nt < 8; nt++)
#pragma unroll
            for (int i = 0; i < 4; i++) acc[mt][nt][i] = 0.f;

    const int T = K / BKH;

    auto issue = [&](int kt, int buf) {
#pragma unroll
        for (int i = 0; i < 2; i++) {
            int r = l_r + 64 * i;
            const __half* gp = A + (size_t)(bm + r) * K + kt + l_c;
            unsigned s = (unsigned)__cvta_generic_to_shared(&As[buf][r * SA + l_c]);
            asm volatile("cp.async.cg.shared.global [%0], [%1], 16;\n" :: "r"(s), "l"(gp));
        }
#pragma unroll
        for (int i = 0; i < 2; i++) {
            int r = l_r + 64 * i;
            const __half* gp = Bt + (size_t)(bn + r) * K + kt + l_c;
            unsigned s = (unsigned)__cvta_generic_to_shared(&Bs[buf][r * SB + l_c]);
            asm volatile("cp.async.cg.shared.global [%0], [%1], 16;\n" :: "r"(s), "l"(gp));
        }
        asm volatile("cp.async.commit_group;\n");
    };

    issue(0, 0);

    for (int t = 0; t < T; t++) {
        if (t + 1 < T) {
            issue((t + 1) * BKH, (t + 1) & 1);
            asm volatile("cp.async.wait_group 1;\n");
        } else {
            asm volatile("cp.async.wait_group 0;\n");
        }
        __syncthreads();

        const unsigned abx = (unsigned)__cvta_generic_to_shared(As[t & 1]);
        const unsigned bbx = (unsigned)__cvta_generic_to_shared(Bs[t & 1]);

#pragma unroll
        for (int kk = 0; kk < 2; kk++) {
            int colA = kk * 16 + (g >> 1) * 8;
            unsigned af[2][4], bf[4][4];
#pragma unroll
            for (int mt = 0; mt < 2; mt++) {
                int row = wm * 32 + mt * 16 + (g & 1) * 8 + j;
                LDSM_X4(af[mt][0], af[mt][1], af[mt][2], af[mt][3],
                        abx + (unsigned)((row * SA + colA) * 2));
            }
#pragma unroll
            for (int p = 0; p < 4; p++) {
                int row = wn * 64 + p * 16 + (g & 1) * 8 + j;
                LDSM_X4(bf[p][0], bf[p][1], bf[p][2], bf[p][3],
                        bbx + (unsigned)((row * SB + colA) * 2));
            }
#pragma unroll
            for (int mt = 0; mt < 2; mt++)
#pragma unroll
                for (int p = 0; p < 4; p++) {
                    MMA16816(acc[mt][2 * p],     af[mt][0], af[mt][1], af[mt][2], af[mt][3],
                             bf[p][0], bf[p][2]);
                    MMA16816(acc[mt][2 * p + 1], af[mt][0], af[mt][1], af[mt][2], af[mt][3],
                             bf[p][1], bf[p][3]);
                }
        }
        __syncthreads();
    }

    if (MODE == 4) {
        // FC2: bias + residual, then transposed write to BCHW via smem staging.
        float* st = reinterpret_cast<float*>(As);  // 128x33 floats (16.9KB) <= As (20.5KB)
        int b = bm >> 12;
        int hw0 = bm & 4095;
        float* ybase = (float*)Cout + ((size_t)b * DIM + bn) * 4096 + hw0;
#pragma unroll
        for (int c = 0; c < 4; c++) {
            if ((c >> 1) == wn) {
                int nt0 = (c & 1) * 4;
#pragma unroll
                for (int mt = 0; mt < 2; mt++)
#pragma unroll
                    for (int hf = 0; hf < 2; hf++) {
                        int ml = wm * 32 + mt * 16 + grp + hf * 8;
                        const float* rr = res + (size_t)(bm + ml) * DIM + bn + c * 32;
#pragma unroll
                        for (int q = 0; q < 4; q++) {
                            int nt = nt0 + q;
                            int nl = q * 8 + lig * 2;
                            int ng = bn + c * 32 + nl;
                            float2 rv = *(const float2*)(rr + nl);
                            st[ml * 33 + nl]     = acc[mt][nt][hf * 2 + 0] + bias[ng] + rv.x;
                            st[ml * 33 + nl + 1] = acc[mt][nt][hf * 2 + 1] + bias[ng + 1] + rv.y;
                        }
                    }
            }
            __syncthreads();
            {
                int nl = tid >> 3;
                int m0 = (tid & 7) << 4;
                float* dst = ybase + (size_t)(c * 32 + nl) * 4096 + m0;
#pragma unroll
                for (int i = 0; i < 4; i++) {
                    float4 o;
                    o.x = st[(m0 + 4 * i + 0) * 33 + nl];
                    o.y = st[(m0 + 4 * i + 1) * 33 + nl];
                    o.z = st[(m0 + 4 * i + 2) * 33 + nl];
                    o.w = st[(m0 + 4 * i + 3) * 33 + nl];
                    *(float4*)(dst + 4 * i) = o;
                }
            }
            __syncthreads();
        }
        return;
    }

#pragma unroll
    for (int mt = 0; mt < 2; mt++) {
#pragma unroll
        for (int half_ = 0; half_ < 2; half_++) {
            int m = bm + wm * 32 + mt * 16 + grp + half_ * 8;
            size_t crow;
            size_t rrow = 0;
            if (MODE == 3) {
                int b = m >> 12, win = (m >> 6) & 63, pos = m & 63;
                int wy = win >> 3, wx = win & 7, iy = pos >> 3, ix = pos & 7;
                int h = (wy * 8 + iy + 4) & 63;
                int w = (wx * 8 + ix + 4) & 63;
                size_t tk = (size_t)b * 4096 + h * 64 + w;
                crow = tk * N;
                rrow = tk * DIM;
            } else {
                crow = (size_t)m * N;
            }
#pragma unroll
            for (int nt = 0; nt < 8; nt++) {
                int n = bn + wn * 64 + nt * 8 + lig * 2;
                float v0 = acc[mt][nt][half_ * 2 + 0] + bias[n];
                float v1 = acc[mt][nt][half_ * 2 + 1] + bias[n + 1];
                if (MODE == 0) {
                    *(__half2*)((__half*)Cout + crow + n) = __floats2half2_rn(v0, v1);
                } else if (MODE == 1) {
                    v0 = 0.5f * v0 * (1.0f + erff(v0 * 0.7071067811865476f));
                    v1 = 0.5f * v1 * (1.0f + erff(v1 * 0.7071067811865476f));
                    *(__half2*)((__half*)Cout + crow + n) = __floats2half2_rn(v0, v1);
                } else {  // MODE 3: + residual, float out
                    v0 += res[rrow + n];
                    v1 += res[rrow + n + 1];
                    *(float2*)((float*)Cout + crow + n) = make_float2(v0, v1);
                }
            }
        }
    }
}

// ---------------- launcher -----------------------------------------------------
extern "C" void kernel_launch(void* const* d_in, const int* in_sizes, int n_in,
                              void* d_out, int out_size) {
    const float* x       = (const float*)d_in[0];
    const float* qkv_w   = (const float*)d_in[1];
    const float* qkv_b   = (const float*)d_in[2];
    const float* proj_w  = (const float*)d_in[3];
    const float* proj_b  = (const float*)d_in[4];
    const float* rel_bias= (const float*)d_in[5];
    const float* norm1_g = (const float*)d_in[6];
    const float* norm1_b = (const float*)d_in[7];
    const float* norm2_g = (const float*)d_in[8];
    const float* norm2_b = (const float*)d_in[9];
    const float* fc1_w   = (const float*)d_in[10];
    const float* fc1_b   = (const float*)d_in[11];
    const float* fc2_w   = (const float*)d_in[12];
    const float* fc2_b   = (const float*)d_in[13];

    float *xt, *x1;
    __half *xw, *qkv, *attout, *h, *wt_qkv, *wt_proj, *wt_fc1, *wt_fc2;
    cudaGetSymbolAddress((void**)&xt, g_xt);
    cudaGetSymbolAddress((void**)&xw, g_xw);
    cudaGetSymbolAddress((void**)&qkv, g_qkv);
    cudaGetSymbolAddress((void**)&attout, g_attout);
    cudaGetSymbolAddress((void**)&x1, g_x1);
    cudaGetSymbolAddress((void**)&h, g_h);
    cudaGetSymbolAddress((void**)&wt_qkv, g_wt_qkv);
    cudaGetSymbolAddress((void**)&wt_proj, g_wt_proj);
    cudaGetSymbolAddress((void**)&wt_fc1, g_wt_fc1);
    cudaGetSymbolAddress((void**)&wt_fc2, g_wt_fc2);

    // 0. all weight transposes, one launch
    transpose_w4<<<dim3(48, 48, 4), dim3(32, 8)>>>(qkv_w, proj_w, fc1_w, fc2_w,
                                                   wt_qkv, wt_proj, wt_fc1, wt_fc2);
    // 1. BCHW -> token-major (shortcut)
    transpose_in<<<dim3(128, 12, 32), dim3(32, 8)>>>(x, xt);
    // 2. LN1 + shift + window partition -> fp16
    ln_kernel<true><<<NTOK / 8, 256>>>(xt, norm1_g, norm1_b, xw);
    // 3. QKV projection -> half
    hgemm<0><<<dim3(QKV_N / 128, NTOK / 128), 256>>>(xw, wt_qkv, qkv_b, nullptr, qkv,
                                                     NTOK, QKV_N, DIM);
    // 4. windowed attention (fp16 mma, register softmax) -> half
    attn_mma<<<2048 * HEADS, 128>>>(qkv, rel_bias, attout);
    // 5. output projection + fused window-reverse/unshift + residual(xt) -> x1
    hgemm<3><<<dim3(DIM / 128, NTOK / 128), 256>>>(attout, wt_proj, proj_b, xt, x1,
                                                   NTOK, DIM, DIM);
    // 6. LN2 -> fp16
    ln_kernel<false><<<NTOK / 8, 256>>>(x1, norm2_g, norm2_b, xw);
    // 7. FC1 + GELU -> fp16
    hgemm<1><<<dim3(MLP_HIDDEN / 128, NTOK / 128), 256>>>(xw, wt_fc1, fc1_b, nullptr, h,
                                                          NTOK, MLP_HIDDEN, DIM);
    // 8. FC2 + residual(x1) -> d_out in BCHW directly (fused transpose)
    hgemm<4><<<dim3(DIM / 128, NTOK / 128), 256>>>(h, wt_fc2, fc2_b, x1, d_out,
                                                   NTOK, DIM, MLP_HIDDEN);
}

// round 8
// speedup vs baseline: 5.2888x; 1.0280x over previous
#include <cuda_runtime.h>
#include <cuda_fp16.h>
#include <cstdint>
#include <math.h>

#define DIM 384
#define HEADS 12
#define HEAD_DIM 32
#define NTOK 131072          // 32*64*64 tokens
#define QKV_N 1152
#define MLP_HIDDEN 1536
#define ATT_SCALE 0.17677669529663687f   // 32^-0.5

// ---------------- scratch (static device globals; no allocations) -------------
__device__ float  g_xt[NTOK * DIM];           // token-major input (shortcut)
__device__ __half g_xw[NTOK * DIM];           // LN output (GEMM A input)
__device__ __half g_qkv[NTOK * QKV_N];        // qkv projections (half)
__device__ __half g_attout[NTOK * DIM];       // attention output (GEMM A input)
__device__ float  g_x1[NTOK * DIM];           // post-attention residual
__device__ __half g_h[NTOK * MLP_HIDDEN];     // MLP hidden (GEMM A input)
// transposed (N,K) weights in fp16
__device__ __half g_wt_qkv[QKV_N * DIM];
__device__ __half g_wt_proj[DIM * DIM];
__device__ __half g_wt_fc1[MLP_HIDDEN * DIM];
__device__ __half g_wt_fc2[DIM * MLP_HIDDEN];

// ---------------- mma / ldmatrix helpers --------------------------------------
#define LDSM_X4(r0, r1, r2, r3, addr) \
    asm volatile("ldmatrix.sync.aligned.m8n8.x4.shared.b16 {%0,%1,%2,%3}, [%4];" \
                 : "=r"(r0), "=r"(r1), "=r"(r2), "=r"(r3) : "r"(addr))
#define LDSM_X4_T(r0, r1, r2, r3, addr) \
    asm volatile("ldmatrix.sync.aligned.m8n8.x4.trans.shared.b16 {%0,%1,%2,%3}, [%4];" \
                 : "=r"(r0), "=r"(r1), "=r"(r2), "=r"(r3) : "r"(addr))
#define MMA16816(d, a0, a1, a2, a3, b0, b1) \
    asm volatile("mma.sync.aligned.m16n8k16.row.col.f32.f16.f16.f32 " \
                 "{%0,%1,%2,%3}, {%4,%5,%6,%7}, {%8,%9}, {%0,%1,%2,%3};" \
                 : "+f"((d)[0]), "+f"((d)[1]), "+f"((d)[2]), "+f"((d)[3]) \
                 : "r"(a0), "r"(a1), "r"(a2), "r"(a3), "r"(b0), "r"(b1))

// ---------------- transpose: (B,C,HW) -> (B,HW,C) ----------------------------
__global__ void transpose_in(const float* __restrict__ x, float* __restrict__ xt) {
    __shared__ float tile[32][33];
    int b = blockIdx.z;
    int c0 = blockIdx.y * 32;
    int p0 = blockIdx.x * 32;
    const float* xb = x + (size_t)b * DIM * 4096;
    float* xtb = xt + (size_t)b * 4096 * DIM;
    int tx = threadIdx.x, ty = threadIdx.y;
#pragma unroll
    for (int i = 0; i < 32; i += 8)
        tile[ty + i][tx] = xb[(size_t)(c0 + ty + i) * 4096 + p0 + tx];
    __syncthreads();
#pragma unroll
    for (int i = 0; i < 32; i += 8)
        xtb[(size_t)(p0 + ty + i) * DIM + c0 + tx] = tile[tx][ty + i];
}

// ---------------- all 4 weight transposes in ONE launch -----------------------
__global__ void transpose_w4(const float* __restrict__ qkv_w, const float* __restrict__ proj_w,
                             const float* __restrict__ fc1_w, const float* __restrict__ fc2_w,
                             __half* __restrict__ wt_qkv, __half* __restrict__ wt_proj,
                             __half* __restrict__ wt_fc1, __half* __restrict__ wt_fc2) {
    __shared__ float tile[32][33];
    int z = blockIdx.z;
    const float* W;
    __half* Wt;
    int K, N;
    if (z == 0)      { W = qkv_w;  Wt = wt_qkv;  K = DIM;        N = QKV_N; }
    else if (z == 1) { W = proj_w; Wt = wt_proj; K = DIM;        N = DIM; }
    else if (z == 2) { W = fc1_w;  Wt = wt_fc1;  K = DIM;        N = MLP_HIDDEN; }
    else             { W = fc2_w;  Wt = wt_fc2;  K = MLP_HIDDEN; N = DIM; }
    int n0 = blockIdx.x * 32;
    int k0 = blockIdx.y * 32;
    if (n0 >= N || k0 >= K) return;
    int tx = threadIdx.x, ty = threadIdx.y;
#pragma unroll
    for (int i = 0; i < 32; i += 8)
        tile[ty + i][tx] = W[(size_t)(k0 + ty + i) * N + n0 + tx];
    __syncthreads();
#pragma unroll
    for (int i = 0; i < 32; i += 8)
        Wt[(size_t)(n0 + ty + i) * K + k0 + tx] = __float2half_rn(tile[tx][ty + i]);
}

// ---------------- LayerNorm (+optional shift+window gather) ------------------
template <bool WINDOWED>
__global__ void ln_kernel(const float* __restrict__ src,
                          const float* __restrict__ gamma,
                          const float* __restrict__ beta,
                          __half* __restrict__ dst) {
    int warp = (blockIdx.x * blockDim.x + threadIdx.x) >> 5;
    int lane = threadIdx.x & 31;
    if (warp >= NTOK) return;

    size_t srow;
    if (WINDOWED) {
        int pos = warp & 63;
        int win = (warp >> 6) & 63;
        int b = warp >> 12;
        int iy = pos >> 3, ix = pos & 7;
        int wy = win >> 3, wx = win & 7;
        int hs = (wy * 8 + iy + 4) & 63;   // roll(-4)
        int ws = (wx * 8 + ix + 4) & 63;
        srow = ((size_t)b * 4096 + hs * 64 + ws) * DIM;
    } else {
        srow = (size_t)warp * DIM;
    }
    const float* row = src + srow;

    float vals[12];
    float s = 0.f;
#pragma unroll
    for (int k = 0; k < 12; k++) { vals[k] = row[lane + k * 32]; s += vals[k]; }
#pragma unroll
    for (int o = 16; o; o >>= 1) s += __shfl_xor_sync(0xffffffffu, s, o);
    float mu = s * (1.f / 384.f);
    float vv = 0.f;
#pragma unroll
    for (int k = 0; k < 12; k++) { float d = vals[k] - mu; vv += d * d; }
#pragma unroll
    for (int o = 16; o; o >>= 1) vv += __shfl_xor_sync(0xffffffffu, vv, o);
    float rstd = rsqrtf(vv * (1.f / 384.f) + 1e-5f);

    __half* orow = dst + (size_t)warp * DIM;
#pragma unroll
    for (int k = 0; k < 12; k++) {
        int c = lane + k * 32;
        orow[c] = __float2half_rn((vals[k] - mu) * rstd * gamma[c] + beta[c]);
    }
}

// ---------------- fused windowed attention (fp16 mma) ------------------------
__device__ __forceinline__ int region64(int v) { return v < 56 ? 0 : (v < 60 ? 1 : 2); }

__device__ __forceinline__ unsigned pkh2(float a, float b) {
    __half2 h = __floats2half2_rn(a, b);
    return *(unsigned*)&h;
}

#define ASTRIDE 40   // halfs per row: conflict-free for ldmatrix

__global__ __launch_bounds__(128) void attn_mma(const __half* __restrict__ qkv,
                                                const float* __restrict__ rel_bias,
                                                __half* __restrict__ out) {
    __shared__ __half Qs[64 * ASTRIDE];
    __shared__ __half Ks[64 * ASTRIDE];
    __shared__ __half Vs[64 * ASTRIDE];
    __shared__ float sbias[225];

    int blk = blockIdx.x;
    int win = blk / HEADS;
    int head = blk - win * HEADS;
    int tid = threadIdx.x;
    int lane = tid & 31, warp = tid >> 5;
    int grp = lane >> 2, lig = lane & 3;

    for (int i = tid; i < 225; i += 128) sbias[i] = rel_bias[i * HEADS + head];

    {   // stage Q,K,V
        int n = tid >> 1;
        int c0 = (tid & 1) << 4;
        const __half* rowp = qkv + (size_t)(win * 64 + n) * QKV_N + head * HEAD_DIM + c0;
        *(uint4*)&Qs[n * ASTRIDE + c0]     = *(const uint4*)(rowp);
        *(uint4*)&Qs[n * ASTRIDE + c0 + 8] = *(const uint4*)(rowp + 8);
        *(uint4*)&Ks[n * ASTRIDE + c0]     = *(const uint4*)(rowp + DIM);
        *(uint4*)&Ks[n * ASTRIDE + c0 + 8] = *(const uint4*)(rowp + DIM + 8);
        *(uint4*)&Vs[n * ASTRIDE + c0]     = *(const uint4*)(rowp + 2 * DIM);
        *(uint4*)&Vs[n * ASTRIDE + c0 + 8] = *(const uint4*)(rowp + 2 * DIM + 8);
    }
    __syncthreads();

    const unsigned qb = (unsigned)__cvta_generic_to_shared(Qs);
    const unsigned kb = (unsigned)__cvta_generic_to_shared(Ks);
    const unsigned vb = (unsigned)__cvta_generic_to_shared(Vs);
    const int g = lane >> 3, j = lane & 7;

    unsigned qa[2][4];
#pragma unroll
    for (int kc = 0; kc < 2; kc++) {
        int row = warp * 16 + (g & 1) * 8 + j;
        int col = kc * 16 + (g >> 1) * 8;
        LDSM_X4(qa[kc][0], qa[kc][1], qa[kc][2], qa[kc][3],
                qb + (unsigned)((row * ASTRIDE + col) * 2));
    }

    float sacc[8][4];
#pragma unroll
    for (int nt = 0; nt < 8; nt++)
#pragma unroll
        for (int i = 0; i < 4; i++) sacc[nt][i] = 0.f;

#pragma unroll
    for (int kc = 0; kc < 2; kc++) {
#pragma unroll
        for (int p = 0; p < 4; p++) {
            unsigned kf[4];
            int row = p * 16 + (g >> 1) * 8 + j;
            int col = kc * 16 + (g & 1) * 8;
            LDSM_X4(kf[0], kf[1], kf[2], kf[3],
                    kb + (unsigned)((row * ASTRIDE + col) * 2));
            MMA16816(sacc[2 * p],     qa[kc][0], qa[kc][1], qa[kc][2], qa[kc][3], kf[0], kf[1]);
            MMA16816(sacc[2 * p + 1], qa[kc][0], qa[kc][1], qa[kc][2], qa[kc][3], kf[2], kf[3]);
        }
    }

    int win_img = win & 63;
    int wy = win_img >> 3, wx = win_img & 7;
    int r_lo = warp * 16 + grp, r_hi = r_lo + 8;
    int ry_lo = r_lo >> 3, rx = r_lo & 7;
    int ry_hi = r_hi >> 3;
    int reg_lo = region64(wy * 8 + ry_lo) * 3 + region64(wx * 8 + rx);
    int reg_hi = region64(wy * 8 + ry_hi) * 3 + region64(wx * 8 + rx);

    float mx_lo = -1e30f, mx_hi = -1e30f;
#pragma unroll
    for (int nt = 0; nt < 8; nt++) {
#pragma unroll
        for (int jj = 0; jj < 2; jj++) {
            int c = nt * 8 + 2 * lig + jj;
            int cy = c >> 3, cx = c & 7;
            int regc = region64(wy * 8 + cy) * 3 + region64(wx * 8 + cx);
            float blo = sbias[(ry_lo - cy + 7) * 15 + (rx - cx + 7)];
            float bhi = sbias[(ry_hi - cy + 7) * 15 + (rx - cx + 7)];
            float vlo = sacc[nt][jj] * ATT_SCALE + blo + (reg_lo != regc ? -10.f : 0.f);
            float vhi = sacc[nt][2 + jj] * ATT_SCALE + bhi + (reg_hi != regc ? -10.f : 0.f);
            sacc[nt][jj] = vlo;
            sacc[nt][2 + jj] = vhi;
            mx_lo = fmaxf(mx_lo, vlo);
            mx_hi = fmaxf(mx_hi, vhi);
        }
    }
    mx_lo = fmaxf(mx_lo, __shfl_xor_sync(0xffffffffu, mx_lo, 1));
    mx_lo = fmaxf(mx_lo, __shfl_xor_sync(0xffffffffu, mx_lo, 2));
    mx_hi = fmaxf(mx_hi, __shfl_xor_sync(0xffffffffu, mx_hi, 1));
    mx_hi = fmaxf(mx_hi, __shfl_xor_sync(0xffffffffu, mx_hi, 2));

    float sm_lo = 0.f, sm_hi = 0.f;
#pragma unroll
    for (int nt = 0; nt < 8; nt++) {
#pragma unroll
        for (int jj = 0; jj < 2; jj++) {
            float elo = __expf(sacc[nt][jj] - mx_lo);
            float ehi = __expf(sacc[nt][2 + jj] - mx_hi);
            sacc[nt][jj] = elo;
            sacc[nt][2 + jj] = ehi;
            sm_lo += elo;
            sm_hi += ehi;
        }
    }
    sm_lo += __shfl_xor_sync(0xffffffffu, sm_lo, 1);
    sm_lo += __shfl_xor_sync(0xffffffffu, sm_lo, 2);
    sm_hi += __shfl_xor_sync(0xffffffffu, sm_hi, 1);
    sm_hi += __shfl_xor_sync(0xffffffffu, sm_hi, 2);
    float inv_lo = 1.f / sm_lo, inv_hi = 1.f / sm_hi;

    float oacc[4][4];
#pragma unroll
    for (int nt = 0; nt < 4; nt++)
#pragma unroll
        for (int i = 0; i < 4; i++) oacc[nt][i] = 0.f;

#pragma unroll
    for (int kc = 0; kc < 4; kc++) {
        unsigned pa[4];
        pa[0] = pkh2(sacc[2 * kc][0] * inv_lo,     sacc[2 * kc][1] * inv_lo);
        pa[1] = pkh2(sacc[2 * kc][2] * inv_hi,     sacc[2 * kc][3] * inv_hi);
        pa[2] = pkh2(sacc[2 * kc + 1][0] * inv_lo, sacc[2 * kc + 1][1] * inv_lo);
        pa[3] = pkh2(sacc[2 * kc + 1][2] * inv_hi, sacc[2 * kc + 1][3] * inv_hi);
#pragma unroll
        for (int q = 0; q < 2; q++) {
            unsigned vf[4];
            int row = kc * 16 + (g & 1) * 8 + j;
            int col = q * 16 + (g >> 1) * 8;
            LDSM_X4_T(vf[0], vf[1], vf[2], vf[3],
                      vb + (unsigned)((row * ASTRIDE + col) * 2));
            MMA16816(oacc[2 * q],     pa[0], pa[1], pa[2], pa[3], vf[0], vf[1]);
            MMA16816(oacc[2 * q + 1], pa[0], pa[1], pa[2], pa[3], vf[2], vf[3]);
        }
    }

#pragma unroll
    for (int nt = 0; nt < 4; nt++) {
        int col = head * HEAD_DIM + nt * 8 + 2 * lig;
        __half2 lo = __floats2half2_rn(oacc[nt][0], oacc[nt][1]);
        __half2 hi = __floats2half2_rn(oacc[nt][2], oacc[nt][3]);
        *(__half2*)&out[(size_t)(win * 64 + r_lo) * DIM + col] = lo;
        *(__half2*)&out[(size_t)(win * 64 + r_hi) * DIM + col] = hi;
    }
}

// ================= fp16 tensor-core GEMM (m16n8k16 mma.sync) =================
// C[M,N] = A[M,K] (half) * Bt[N,K]^T (half) + bias.
// 4-stage cp.async circular pipeline, one __syncthreads per k-tile.
// MODE 0: half out. MODE 1: GELU, half out.
// MODE 3: window-reverse+unshift residual, float out (token order).
// MODE 4: +res, write BCHW (transposed, smem-staged), float out = d_out.
#define BKH 32
#define SA 40
#define SB 40
#define STAGES 4
#define HG_SMEM (STAGES * 128 * (SA + SB) * 2)

template <int MODE>
__global__ __launch_bounds__(256, 2) void hgemm(const __half* __restrict__ A,
                                                const __half* __restrict__ Bt,
                                                const float* __restrict__ bias,
                                                const float* __restrict__ res,
                                                void* __restrict__ Cout,
                                                int M, int N, int K) {
    extern __shared__ __half dsm[];
    __half* Asb = dsm;                          // STAGES * 128*SA
    __half* Bsb = dsm + STAGES * 128 * SA;      // STAGES * 128*SB

    const int tid = threadIdx.x;
    const int lane = tid & 31;
    const int wid = tid >> 5;
    const int grp = lane >> 2;
    const int lig = lane & 3;
    const int g = lane >> 3;
    const int j = lane & 7;
    const int wm = wid & 3;
    const int wn = wid >> 2;
    const int bm = blockIdx.y * 128;
    const int bn = blockIdx.x * 128;

    const int l_r = tid >> 2;
    const int l_c = (tid & 3) << 3;

    float acc[2][8][4];
#pragma unroll
    for (int mt = 0; mt < 2; mt++)
#pragma unroll
        for (int nt = 0; nt < 8; nt++)
#pragma unroll
            for (int i = 0; i < 4; i++) acc[mt][nt][i] = 0.f;

    const int T = K / BKH;

    auto issue = [&](int t) {
        if (t < T) {
            int kt = t * BKH;
            int buf = t & (STAGES - 1);
            __half* Ad = Asb + buf * 128 * SA;
            __half* Bd = Bsb + buf * 128 * SB;
#pragma unroll
            for (int i = 0; i < 2; i++) {
                int r = l_r + 64 * i;
                const __half* gp = A + (size_t)(bm + r) * K + kt + l_c;
                unsigned s = (unsigned)__cvta_generic_to_shared(&Ad[r * SA + l_c]);
                asm volatile("cp.async.cg.shared.global [%0], [%1], 16;\n" :: "r"(s), "l"(gp));
            }
#pragma unroll
            for (int i = 0; i < 2; i++) {
                int r = l_r + 64 * i;
                const __half* gp = Bt + (size_t)(bn + r) * K + kt + l_c;
                unsigned s = (unsigned)__cvta_generic_to_shared(&Bd[r * SB + l_c]);
                asm volatile("cp.async.cg.shared.global [%0], [%1], 16;\n" :: "r"(s), "l"(gp));
            }
        }
        asm volatile("cp.async.commit_group;\n");
    };

    issue(0);
    issue(1);
    issue(2);

    for (int t = 0; t < T; t++) {
        asm volatile("cp.async.wait_group %0;\n" :: "n"(STAGES - 2) : "memory");
        __syncthreads();
        issue(t + STAGES - 1);

        int buf = t & (STAGES - 1);
        const unsigned abx = (unsigned)__cvta_generic_to_shared(Asb + buf * 128 * SA);
        const unsigned bbx = (unsigned)__cvta_generic_to_shared(Bsb + buf * 128 * SB);

#pragma unroll
        for (int kk = 0; kk < 2; kk++) {
            int colA = kk * 16 + (g >> 1) * 8;
            unsigned af[2][4], bf[4][4];
#pragma unroll
            for (int mt = 0; mt < 2; mt++) {
                int row = wm * 32 + mt * 16 + (g & 1) * 8 + j;
                LDSM_X4(af[mt][0], af[mt][1], af[mt][2], af[mt][3],
                        abx + (unsigned)((row * SA + colA) * 2));
            }
#pragma unroll
            for (int p = 0; p < 4; p++) {
                int row = wn * 64 + p * 16 + (g & 1) * 8 + j;
                LDSM_X4(bf[p][0], bf[p][1], bf[p][2], bf[p][3],
                        bbx + (unsigned)((row * SB + colA) * 2));
            }
#pragma unroll
            for (int mt = 0; mt < 2; mt++)
#pragma unroll
                for (int p = 0; p < 4; p++) {
                    MMA16816(acc[mt][2 * p],     af[mt][0], af[mt][1], af[mt][2], af[mt][3],
                             bf[p][0], bf[p][2]);
                    MMA16816(acc[mt][2 * p + 1], af[mt][0], af[mt][1], af[mt][2], af[mt][3],
                             bf[p][1], bf[p][3]);
                }
        }
    }
    __syncthreads();

    if (MODE == 4) {
        // FC2: bias + residual, then transposed write to BCHW via smem staging.
        float* st = reinterpret_cast<float*>(Asb);  // 128x33 floats (16.9KB)
        int b = bm >> 12;
        int hw0 = bm & 4095;
        float* ybase = (float*)Cout + ((size_t)b * DIM + bn) * 4096 + hw0;
#pragma unroll
        for (int c = 0; c < 4; c++) {
            if ((c >> 1) == wn) {
                int nt0 = (c & 1) * 4;
#pragma unroll
                for (int mt = 0; mt < 2; mt++)
#pragma unroll
                    for (int hf = 0; hf < 2; hf++) {
                        int ml = wm * 32 + mt * 16 + grp + hf * 8;
                        const float* rr = res + (size_t)(bm + ml) * DIM + bn + c * 32;
#pragma unroll
                        for (int q = 0; q < 4; q++) {
                            int nt = nt0 + q;
                            int nl = q * 8 + lig * 2;
                            int ng = bn + c * 32 + nl;
                            float2 rv = *(const float2*)(rr + nl);
                            st[ml * 33 + nl]     = acc[mt][nt][hf * 2 + 0] + bias[ng] + rv.x;
                            st[ml * 33 + nl + 1] = acc[mt][nt][hf * 2 + 1] + bias[ng + 1] + rv.y;
                        }
                    }
            }
            __syncthreads();
            {
                int nl = tid >> 3;
                int m0 = (tid & 7) << 4;
                float* dst = ybase + (size_t)(c * 32 + nl) * 4096 + m0;
#pragma unroll
                for (int i = 0; i < 4; i++) {
                    float4 o;
                    o.x = st[(m0 + 4 * i + 0) * 33 + nl];
                    o.y = st[(m0 + 4 * i + 1) * 33 + nl];
                    o.z = st[(m0 + 4 * i + 2) * 33 + nl];
                    o.w = st[(m0 + 4 * i + 3) * 33 + nl];
                    *(float4*)(dst + 4 * i) = o;
                }
            }
            __syncthreads();
        }
        return;
    }

#pragma unroll
    for (int mt = 0; mt < 2; mt++) {
#pragma unroll
        for (int half_ = 0; half_ < 2; half_++) {
            int m = bm + wm * 32 + mt * 16 + grp + half_ * 8;
            size_t crow;
            size_t rrow = 0;
            if (MODE == 3) {
                int b = m >> 12, win = (m >> 6) & 63, pos = m & 63;
                int wy = win >> 3, wx = win & 7, iy = pos >> 3, ix = pos & 7;
                int h = (wy * 8 + iy + 4) & 63;
                int w = (wx * 8 + ix + 4) & 63;
                size_t tk = (size_t)b * 4096 + h * 64 + w;
                crow = tk * N;
                rrow = tk * DIM;
            } else {
                crow = (size_t)m * N;
            }
#pragma unroll
            for (int nt = 0; nt < 8; nt++) {
                int n = bn + wn * 64 + nt * 8 + lig * 2;
                float v0 = acc[mt][nt][half_ * 2 + 0] + bias[n];
                float v1 = acc[mt][nt][half_ * 2 + 1] + bias[n + 1];
                if (MODE == 0) {
                    *(__half2*)((__half*)Cout + crow + n) = __floats2half2_rn(v0, v1);
                } else if (MODE == 1) {
                    v0 = 0.5f * v0 * (1.0f + erff(v0 * 0.7071067811865476f));
                    v1 = 0.5f * v1 * (1.0f + erff(v1 * 0.7071067811865476f));
                    *(__half2*)((__half*)Cout + crow + n) = __floats2half2_rn(v0, v1);
                } else {  // MODE 3: + residual, float out
                    v0 += res[rrow + n];
                    v1 += res[rrow + n + 1];
                    *(float2*)((float*)Cout + crow + n) = make_float2(v0, v1);
                }
            }
        }
    }
}

// ---------------- launcher -----------------------------------------------------
extern "C" void kernel_launch(void* const* d_in, const int* in_sizes, int n_in,
                              void* d_out, int out_size) {
    const float* x       = (const float*)d_in[0];
    const float* qkv_w   = (const float*)d_in[1];
    const float* qkv_b   = (const float*)d_in[2];
    const float* proj_w  = (const float*)d_in[3];
    const float* proj_b  = (const float*)d_in[4];
    const float* rel_bias= (const float*)d_in[5];
    const float* norm1_g = (const float*)d_in[6];
    const float* norm1_b = (const float*)d_in[7];
    const float* norm2_g = (const float*)d_in[8];
    const float* norm2_b = (const float*)d_in[9];
    const float* fc1_w   = (const float*)d_in[10];
    const float* fc1_b   = (const float*)d_in[11];
    const float* fc2_w   = (const float*)d_in[12];
    const float* fc2_b   = (const float*)d_in[13];

    float *xt, *x1;
    __half *xw, *qkv, *attout, *h, *wt_qkv, *wt_proj, *wt_fc1, *wt_fc2;
    cudaGetSymbolAddress((void**)&xt, g_xt);
    cudaGetSymbolAddress((void**)&xw, g_xw);
    cudaGetSymbolAddress((void**)&qkv, g_qkv);
    cudaGetSymbolAddress((void**)&attout, g_attout);
    cudaGetSymbolAddress((void**)&x1, g_x1);
    cudaGetSymbolAddress((void**)&h, g_h);
    cudaGetSymbolAddress((void**)&wt_qkv, g_wt_qkv);
    cudaGetSymbolAddress((void**)&wt_proj, g_wt_proj);
    cudaGetSymbolAddress((void**)&wt_fc1, g_wt_fc1);
    cudaGetSymbolAddress((void**)&wt_fc2, g_wt_fc2);

    cudaFuncSetAttribute(hgemm<0>, cudaFuncAttributeMaxDynamicSharedMemorySize, HG_SMEM);
    cudaFuncSetAttribute(hgemm<1>, cudaFuncAttributeMaxDynamicSharedMemorySize, HG_SMEM);
    cudaFuncSetAttribute(hgemm<3>, cudaFuncAttributeMaxDynamicSharedMemorySize, HG_SMEM);
    cudaFuncSetAttribute(hgemm<4>, cudaFuncAttributeMaxDynamicSharedMemorySize, HG_SMEM);

    // 0. all weight transposes, one launch
    transpose_w4<<<dim3(48, 48, 4), dim3(32, 8)>>>(qkv_w, proj_w, fc1_w, fc2_w,
                                                   wt_qkv, wt_proj, wt_fc1, wt_fc2);
    // 1. BCHW -> token-major (shortcut)
    transpose_in<<<dim3(128, 12, 32), dim3(32, 8)>>>(x, xt);
    // 2. LN1 + shift + window partition -> fp16
    ln_kernel<true><<<NTOK / 8, 256>>>(xt, norm1_g, norm1_b, xw);
    // 3. QKV projection -> half
    hgemm<0><<<dim3(QKV_N / 128, NTOK / 128), 256, HG_SMEM>>>(xw, wt_qkv, qkv_b, nullptr, qkv,
                                                              NTOK, QKV_N, DIM);
    // 4. windowed attention (fp16 mma, register softmax) -> half
    attn_mma<<<2048 * HEADS, 128>>>(qkv, rel_bias, attout);
    // 5. output projection + fused window-reverse/unshift + residual(xt) -> x1
    hgemm<3><<<dim3(DIM / 128, NTOK / 128), 256, HG_SMEM>>>(attout, wt_proj, proj_b, xt, x1,
                                                            NTOK, DIM, DIM);
    // 6. LN2 -> fp16
    ln_kernel<false><<<NTOK / 8, 256>>>(x1, norm2_g, norm2_b, xw);
    // 7. FC1 + GELU -> fp16
    hgemm<1><<<dim3(MLP_HIDDEN / 128, NTOK / 128), 256, HG_SMEM>>>(xw, wt_fc1, fc1_b, nullptr, h,
                                                                   NTOK, MLP_HIDDEN, DIM);
    // 8. FC2 + residual(x1) -> d_out in BCHW directly (fused transpose)
    hgemm<4><<<dim3(DIM / 128, NTOK / 128), 256, HG_SMEM>>>(h, wt_fc2, fc2_b, x1, d_out,
                                                            NTOK, DIM, MLP_HIDDEN);
}